// round 11
// baseline (speedup 1.0000x reference)
#include <cuda_runtime.h>
#include <cuda_bf16.h>

#define BB 8192
#define NMAPC 15625
typedef unsigned int u32;

// ---------------- scratch (static device globals: allocation-free) ----------
__device__ int   d_owner[NMAPC];
__device__ float d_h1[(size_t)BB * 3 * 256];
__device__ float d_h2[(size_t)BB * 2 * 256];
__device__ float d_g [(size_t)BB * 256];
__device__ float d_part[64 * 256];
__device__ float d_cvec[256];
// fragment-ordered bf16 weights: [mat][kt(16)][nt(32)][lane(32)][reg(2)] u32
__device__ __align__(16) u32 d_BfragH[4 * 32768];
__device__ __align__(16) u32 d_BfragL[4 * 32768];

// ---------------- helpers ---------------------------------------------------
__device__ __forceinline__ float4 f4add(float4 a, float4 b) {
    return make_float4(a.x + b.x, a.y + b.y, a.z + b.z, a.w + b.w);
}
__device__ __forceinline__ u32 pack_bf2(float lo, float hi) {
    __nv_bfloat16 a = __float2bfloat16(lo), b = __float2bfloat16(hi);
    return ((u32)__bfloat16_as_ushort(b) << 16) | __bfloat16_as_ushort(a);
}
__device__ __forceinline__ void mma16816(float* c, const u32* a, const u32* b) {
    asm volatile(
        "mma.sync.aligned.m16n8k16.row.col.f32.bf16.bf16.f32 "
        "{%0,%1,%2,%3}, {%4,%5,%6,%7}, {%8,%9}, {%0,%1,%2,%3};"
        : "+f"(c[0]), "+f"(c[1]), "+f"(c[2]), "+f"(c[3])
        : "r"(a[0]), "r"(a[1]), "r"(a[2]), "r"(a[3]), "r"(b[0]), "r"(b[1]));
}

// ---------------- small kernels ---------------------------------------------
__global__ void k_init() {
    int i = blockIdx.x * 256 + threadIdx.x;
    if (i < NMAPC) d_owner[i] = -1;
}
__global__ void k_setowner(const int* __restrict__ key_ids) {
    int b = blockIdx.x * 256 + threadIdx.x;
    if (b < BB) {
        const int* kd = key_ids + b * 6;
        int idx = kd[0]*3125 + kd[1]*625 + kd[2]*125 + kd[3]*25 + kd[4]*5 + kd[5];
        d_owner[idx] = b;
    }
}
// W -> bf16 hi/lo fragment images (mma m16n8k16 B-layout, per-lane order)
__global__ void k_prepW(const float* __restrict__ sage_W, const float* __restrict__ pW1) {
    int t = blockIdx.x * 256 + threadIdx.x;   // 131072 threads
    int rg  = t & 1;
    int l   = (t >> 1) & 31;
    int nt  = (t >> 6) & 31;
    int kt  = (t >> 11) & 15;
    int mat = t >> 15;
    const float* src = (mat < 3) ? (sage_W + (size_t)mat * 65536) : pW1;
    int n  = nt * 8 + (l >> 2);
    int k0 = kt * 16 + (l & 3) * 2 + rg * 8;
    float x0 = src[(size_t)k0 * 256 + n];
    float x1 = src[(size_t)(k0 + 1) * 256 + n];
    __nv_bfloat16 h0 = __float2bfloat16(x0), h1 = __float2bfloat16(x1);
    float l0 = x0 - __bfloat162float(h0), l1 = x1 - __bfloat162float(h1);
    int di = mat * 32768 + ((kt * 32 + nt) * 32 + l) * 2 + rg;
    d_BfragH[di] = ((u32)__bfloat16_as_ushort(h1) << 16) | __bfloat16_as_ushort(h0);
    d_BfragL[di] = pack_bf2(l0, l1);
}

// ---------------- fused HMMA GEMM -------------------------------------------
// CTA: 64 rows x 256 cols, 512 threads = 16 warps (2M x 8N), warp tile 32x32.
// 4 warps/SMSP for latency coverage; B register-prefetched one kt ahead.
#define AH_OFF 0
#define AL_OFF 33792
#define SS_OFF 67584
#define SMEM_D (67584 + 4608)

template<int MODE>
__global__ __launch_bounds__(512) void gemm_fused(
    int mat,
    const float* __restrict__ bias, const float* __restrict__ gamma, const float* __restrict__ beta,
    const int* __restrict__ features, const float* __restrict__ emb,
    const float* __restrict__ w2, const float* __restrict__ w2b,
    float* __restrict__ outp)
{
    extern __shared__ __align__(16) char smem[];
    u32* ah32 = (u32*)(smem + AH_OFF);          // [64][264] bf16 viewed as u32 pairs
    u32* al32 = (u32*)(smem + AL_OFF);
    float* ssum  = (float*)(smem + SS_OFF);     // [8][64]
    float* ssq   = ssum + 512;                  // [8][64]
    float* meanv = ssq + 512;                   // [64]
    float* rsdv  = meanv + 64;                  // [64]

    const int tid = threadIdx.x, lane = tid & 31, warp = tid >> 5;
    const int wm = warp >> 3, wn = warp & 7;    // 2M x 8N
    const int m0 = blockIdx.x * 64;

    // ---- A prologue: aggregate fp32, split hi/lo bf16, stage in smem
    {
        int row = tid >> 3, cb = (tid & 7) * 32;
        int m = m0 + row;
        const float* s0; const float* s1 = nullptr; const float* s2 = nullptr;
        float scl = 1.f;
        if (MODE == 1) {
            int b = m / 3, j = m - 3 * b;
            const int* f = features + b * 9;
            int lo = (j == 0) ? 0 : (j - 1);
            s0 = emb + f[lo] * 256;
            s1 = emb + f[lo + 1] * 256;
            if (j) s2 = emb + f[lo + 2] * 256;
            scl = j ? (1.f / 3.f) : 0.5f;
        } else if (MODE == 2) {
            const float* base = d_h1 + (size_t)(m >> 1) * 768;
            s0 = base; s1 = base + 256;
            if (m & 1) s2 = base + 512;
            scl = (m & 1) ? (1.f / 3.f) : 0.5f;
        } else if (MODE == 3) {
            const float* base = d_h2 + (size_t)m * 512;
            s0 = base; s1 = base + 256; scl = 0.5f;
        } else {
            s0 = d_g + (size_t)m * 256;
        }
#pragma unroll
        for (int i = 0; i < 8; i++) {
            float4 a = *(const float4*)&s0[cb + 4 * i];
            if (MODE != 4) {
                a = f4add(a, *(const float4*)&s1[cb + 4 * i]);
                if (s2) a = f4add(a, *(const float4*)&s2[cb + 4 * i]);
                a.x *= scl; a.y *= scl; a.z *= scl; a.w *= scl;
            }
            __nv_bfloat16 hx = __float2bfloat16(a.x), hy = __float2bfloat16(a.y);
            __nv_bfloat16 hz = __float2bfloat16(a.z), hw = __float2bfloat16(a.w);
            int off = row * 264 + cb + 4 * i;      // bf16 offset, even
            ah32[(off >> 1)]     = ((u32)__bfloat16_as_ushort(hy) << 16) | __bfloat16_as_ushort(hx);
            ah32[(off >> 1) + 1] = ((u32)__bfloat16_as_ushort(hw) << 16) | __bfloat16_as_ushort(hz);
            al32[(off >> 1)]     = pack_bf2(a.x - __bfloat162float(hx), a.y - __bfloat162float(hy));
            al32[(off >> 1) + 1] = pack_bf2(a.z - __bfloat162float(hz), a.w - __bfloat162float(hw));
        }
    }
    __syncthreads();

    // ---- main loop with 1-deep register prefetch of B fragments
    float acc[2][4][4];
#pragma unroll
    for (int mt = 0; mt < 2; mt++)
#pragma unroll
        for (int nt = 0; nt < 4; nt++)
#pragma unroll
            for (int q = 0; q < 4; q++) acc[mt][nt][q] = 0.f;

    const int bbase = mat * 32768 + ((wn * 4) * 32 + lane) * 2;   // + kt*2048 + nt*64
    const u32* BH = d_BfragH + bbase;
    const u32* BL = d_BfragL + bbase;
    const int arow = wm * 32 + (lane >> 2);

    u32 bh[2][4][2], bl[2][4][2];
#pragma unroll
    for (int nt = 0; nt < 4; nt++) {
        uint2 vh = *(const uint2*)&BH[nt * 64];
        uint2 vl = *(const uint2*)&BL[nt * 64];
        bh[0][nt][0] = vh.x; bh[0][nt][1] = vh.y;
        bl[0][nt][0] = vl.x; bl[0][nt][1] = vl.y;
    }

#pragma unroll
    for (int kt = 0; kt < 16; kt++) {
        const int cur = kt & 1, nxt = cur ^ 1;
        // prefetch kt+1 B fragments
        if (kt < 15) {
            int o = (kt + 1) * 2048;
#pragma unroll
            for (int nt = 0; nt < 4; nt++) {
                uint2 vh = *(const uint2*)&BH[o + nt * 64];
                bh[nxt][nt][0] = vh.x; bh[nxt][nt][1] = vh.y;
            }
#pragma unroll
            for (int nt = 0; nt < 4; nt++) {
                uint2 vl = *(const uint2*)&BL[o + nt * 64];
                bl[nxt][nt][0] = vl.x; bl[nxt][nt][1] = vl.y;
            }
        }
        // A fragments (smem)
        u32 ah[2][4], al[2][4];
        int acol = kt * 16 + (lane & 3) * 2;
#pragma unroll
        for (int mt = 0; mt < 2; mt++) {
            int base = (arow + mt * 16) * 264 + acol;   // bf16 offset (even)
            ah[mt][0] = ah32[(base) >> 1];
            ah[mt][1] = ah32[(base + 8 * 264) >> 1];
            ah[mt][2] = ah32[(base + 8) >> 1];
            ah[mt][3] = ah32[(base + 8 * 264 + 8) >> 1];
            al[mt][0] = al32[(base) >> 1];
            al[mt][1] = al32[(base + 8 * 264) >> 1];
            al[mt][2] = al32[(base + 8) >> 1];
            al[mt][3] = al32[(base + 8 * 264 + 8) >> 1];
        }
        // 3 passes over 8 distinct accumulators each
#pragma unroll
        for (int mt = 0; mt < 2; mt++)
#pragma unroll
            for (int nt = 0; nt < 4; nt++)
                mma16816(acc[mt][nt], ah[mt], bh[cur][nt]);
#pragma unroll
        for (int mt = 0; mt < 2; mt++)
#pragma unroll
            for (int nt = 0; nt < 4; nt++)
                mma16816(acc[mt][nt], al[mt], bh[cur][nt]);
#pragma unroll
        for (int mt = 0; mt < 2; mt++)
#pragma unroll
            for (int nt = 0; nt < 4; nt++)
                mma16816(acc[mt][nt], ah[mt], bl[cur][nt]);
    }

    // ---- epilogue. lane owns cols c = wn*32 + nt*8 + (lane&3)*2 (+1),
    //      rows r = wm*32 + mt*16 + lane/4 (regs 0,1) and r+8 (regs 2,3)
    if (MODE <= 3) {
        float bv[4][2];
#pragma unroll
        for (int nt = 0; nt < 4; nt++) {
            int c = wn * 32 + nt * 8 + (lane & 3) * 2;
            bv[nt][0] = bias[c]; bv[nt][1] = bias[c + 1];
        }
#pragma unroll
        for (int mt = 0; mt < 2; mt++) {
            float sL = 0.f, qL = 0.f, sH = 0.f, qH = 0.f;
#pragma unroll
            for (int nt = 0; nt < 4; nt++) {
                float v0 = acc[mt][nt][0] + bv[nt][0], v1 = acc[mt][nt][1] + bv[nt][1];
                float v2 = acc[mt][nt][2] + bv[nt][0], v3 = acc[mt][nt][3] + bv[nt][1];
                sL += v0 + v1; qL += v0 * v0 + v1 * v1;
                sH += v2 + v3; qH += v2 * v2 + v3 * v3;
            }
#pragma unroll
            for (int o = 1; o <= 2; o <<= 1) {
                sL += __shfl_xor_sync(0xffffffffu, sL, o);
                qL += __shfl_xor_sync(0xffffffffu, qL, o);
                sH += __shfl_xor_sync(0xffffffffu, sH, o);
                qH += __shfl_xor_sync(0xffffffffu, qH, o);
            }
            if ((lane & 3) == 0) {
                int r = wm * 32 + mt * 16 + (lane >> 2);
                ssum[wn * 64 + r] = sL;     ssq[wn * 64 + r] = qL;
                ssum[wn * 64 + r + 8] = sH; ssq[wn * 64 + r + 8] = qH;
            }
        }
        __syncthreads();
        if (tid < 64) {
            float s = 0.f, q = 0.f;
#pragma unroll
            for (int w = 0; w < 8; w++) { s += ssum[w * 64 + tid]; q += ssq[w * 64 + tid]; }
            float mean = s * (1.f / 256.f);
            float var  = q * (1.f / 256.f) - mean * mean;
            meanv[tid] = mean;
            rsdv[tid]  = rsqrtf(var + 1e-5f);
        }
        __syncthreads();
        float* O = (MODE == 1) ? d_h1 : ((MODE == 2) ? d_h2 : d_g);
#pragma unroll
        for (int mt = 0; mt < 2; mt++) {
            int r = wm * 32 + mt * 16 + (lane >> 2);
            float mn0 = meanv[r], rs0 = rsdv[r];
            float mn1 = meanv[r + 8], rs1 = rsdv[r + 8];
#pragma unroll
            for (int nt = 0; nt < 4; nt++) {
                int c = wn * 32 + nt * 8 + (lane & 3) * 2;
                float g0 = gamma[c], g1 = gamma[c + 1];
                float b0 = beta[c],  b1 = beta[c + 1];
                float v0 = acc[mt][nt][0] + bv[nt][0], v1 = acc[mt][nt][1] + bv[nt][1];
                float v2 = acc[mt][nt][2] + bv[nt][0], v3 = acc[mt][nt][3] + bv[nt][1];
                float2 oL = make_float2(fmaxf((v0 - mn0) * rs0 * g0 + b0, 0.f),
                                        fmaxf((v1 - mn0) * rs0 * g1 + b1, 0.f));
                float2 oH = make_float2(fmaxf((v2 - mn1) * rs1 * g0 + b0, 0.f),
                                        fmaxf((v3 - mn1) * rs1 * g1 + b1, 0.f));
                *(float2*)&O[(size_t)(m0 + r) * 256 + c]     = oL;
                *(float2*)&O[(size_t)(m0 + r + 8) * 256 + c] = oH;
            }
        }
    } else {
        float cv[4][2], wv[4][2];
#pragma unroll
        for (int nt = 0; nt < 4; nt++) {
            int c = wn * 32 + nt * 8 + (lane & 3) * 2;
            cv[nt][0] = d_cvec[c]; cv[nt][1] = d_cvec[c + 1];
            wv[nt][0] = w2[c];     wv[nt][1] = w2[c + 1];
        }
#pragma unroll
        for (int mt = 0; mt < 2; mt++) {
            float pL = 0.f, pH = 0.f;
#pragma unroll
            for (int nt = 0; nt < 4; nt++) {
                pL = fmaf(fmaxf(acc[mt][nt][0] + cv[nt][0], 0.f), wv[nt][0], pL);
                pL = fmaf(fmaxf(acc[mt][nt][1] + cv[nt][1], 0.f), wv[nt][1], pL);
                pH = fmaf(fmaxf(acc[mt][nt][2] + cv[nt][0], 0.f), wv[nt][0], pH);
                pH = fmaf(fmaxf(acc[mt][nt][3] + cv[nt][1], 0.f), wv[nt][1], pH);
            }
#pragma unroll
            for (int o = 1; o <= 2; o <<= 1) {
                pL += __shfl_xor_sync(0xffffffffu, pL, o);
                pH += __shfl_xor_sync(0xffffffffu, pH, o);
            }
            if ((lane & 3) == 0) {
                int r = wm * 32 + mt * 16 + (lane >> 2);
                ssum[wn * 64 + r] = pL;
                ssum[wn * 64 + r + 8] = pH;
            }
        }
        __syncthreads();
        if (tid < 64) {
            float p = 0.f;
#pragma unroll
            for (int w = 0; w < 8; w++) p += ssum[w * 64 + tid];
            outp[m0 + tid] = p + w2b[0];
        }
    }
}

// ---------------- dnn-device graph (tiny, fp32) -----------------------------
__global__ void k_accum(const int* __restrict__ dd_src) {
    int c = threadIdx.x;
    int e0 = blockIdx.x * 32;
    float loc = 0.f;
    for (int i = 0; i < 32; i++) {
        int o = d_owner[dd_src[e0 + i]];
        if (o >= 0) loc += d_g[(size_t)o * 256 + c];
    }
    d_part[blockIdx.x * 256 + c] = loc;
}

__global__ void k_device(const float* __restrict__ aug,  const float* __restrict__ infoW,
                         const float* __restrict__ infob,
                         const float* __restrict__ ddW,  const float* __restrict__ ddb,
                         const float* __restrict__ ng,   const float* __restrict__ nb,
                         const float* __restrict__ pW1,  const float* __restrict__ pb1) {
    __shared__ float t[256], dev[256], rsum[8], rssq[8];
    int c = threadIdx.x, lane = c & 31, warp = c >> 5;

    float agg = 0.f;
    for (int i = 0; i < 64; i++) agg += d_part[i * 256 + c];

    float info = infob[c];
#pragma unroll
    for (int j = 0; j < 5; j++) info = fmaf(aug[j], infoW[j * 256 + c], info);

    t[c] = (agg + info) * (1.f / 2049.f);
    __syncthreads();

    float acc = ddb[c];
    for (int k = 0; k < 256; k++) acc = fmaf(t[k], ddW[k * 256 + c], acc);

    float s = acc, ss = acc * acc;
#pragma unroll
    for (int o = 16; o > 0; o >>= 1) {
        s  += __shfl_xor_sync(0xffffffffu, s, o);
        ss += __shfl_xor_sync(0xffffffffu, ss, o);
    }
    if (lane == 0) { rsum[warp] = s; rssq[warp] = ss; }
    __syncthreads();
    if (c == 0) {
        float S = 0.f, SS = 0.f;
        for (int i = 0; i < 8; i++) { S += rsum[i]; SS += rssq[i]; }
        rsum[0] = S; rssq[0] = SS;
    }
    __syncthreads();
    float mean = rsum[0] * (1.f / 256.f);
    float var  = rssq[0] * (1.f / 256.f) - mean * mean;
    float rsd  = rsqrtf(var + 1e-5f);
    dev[c] = fmaxf((acc - mean) * rsd * ng[c] + nb[c], 0.f);
    __syncthreads();

    float cv = pb1[c];
    for (int k = 0; k < 256; k++) cv = fmaf(dev[k], pW1[(size_t)(256 + k) * 256 + c], cv);
    d_cvec[c] = cv;
}

// ---------------- launch ----------------------------------------------------
extern "C" void kernel_launch(void* const* d_in, const int* in_sizes, int n_in,
                              void* d_out, int out_size) {
    const int*   features = (const int*)  d_in[0];
    const int*   key_ids  = (const int*)  d_in[1];
    const int*   dd_src   = (const int*)  d_in[4];
    const float* emb      = (const float*)d_in[5];
    const float* sage_W   = (const float*)d_in[6];
    const float* sage_b   = (const float*)d_in[7];
    const float* ln_g     = (const float*)d_in[8];
    const float* ln_b     = (const float*)d_in[9];
    const float* dd_W     = (const float*)d_in[10];
    const float* dd_b     = (const float*)d_in[11];
    const float* norm_g   = (const float*)d_in[12];
    const float* norm_b   = (const float*)d_in[13];
    const float* info_W   = (const float*)d_in[14];
    const float* info_b   = (const float*)d_in[15];
    const float* aug      = (const float*)d_in[16];
    const float* pW1      = (const float*)d_in[17];
    const float* pb1      = (const float*)d_in[18];
    const float* pW2      = (const float*)d_in[19];
    const float* pb2      = (const float*)d_in[20];
    float* out = (float*)d_out;

    static bool attr_done = false;
    if (!attr_done) {
        cudaFuncSetAttribute(gemm_fused<1>, cudaFuncAttributeMaxDynamicSharedMemorySize, SMEM_D);
        cudaFuncSetAttribute(gemm_fused<2>, cudaFuncAttributeMaxDynamicSharedMemorySize, SMEM_D);
        cudaFuncSetAttribute(gemm_fused<3>, cudaFuncAttributeMaxDynamicSharedMemorySize, SMEM_D);
        cudaFuncSetAttribute(gemm_fused<4>, cudaFuncAttributeMaxDynamicSharedMemorySize, SMEM_D);
        attr_done = true;
    }

    k_init<<<(NMAPC + 255) / 256, 256>>>();
    k_setowner<<<BB / 256, 256>>>(key_ids);
    k_prepW<<<512, 256>>>(sage_W, pW1);

    gemm_fused<1><<<384, 512, SMEM_D>>>(0, sage_b,       ln_g,       ln_b,
                                        features, emb, nullptr, nullptr, nullptr);
    gemm_fused<2><<<256, 512, SMEM_D>>>(1, sage_b + 256, ln_g + 256, ln_b + 256,
                                        nullptr, nullptr, nullptr, nullptr, nullptr);
    gemm_fused<3><<<128, 512, SMEM_D>>>(2, sage_b + 512, ln_g + 512, ln_b + 512,
                                        nullptr, nullptr, nullptr, nullptr, nullptr);

    k_accum<<<64, 256>>>(dd_src);
    k_device<<<1, 256>>>(aug, info_W, info_b, dd_W, dd_b, norm_g, norm_b, pW1, pb1);

    gemm_fused<4><<<128, 512, SMEM_D>>>(3, nullptr, nullptr, nullptr,
                                        nullptr, nullptr, pW2, pb2, out);
}

// round 13
// speedup vs baseline: 1.3917x; 1.3917x over previous
#include <cuda_runtime.h>
#include <cuda_bf16.h>

#define BB 8192
#define NMAPC 15625
typedef unsigned int u32;

// ---------------- scratch (static device globals: allocation-free) ----------
__device__ int   d_owner[NMAPC];
__device__ float d_EW[6 * 256];               // emb @ sage_W[0]
__device__ float d_h1[(size_t)BB * 3 * 256];
__device__ float d_h2[(size_t)BB * 2 * 256];
__device__ float d_g [(size_t)BB * 256];
__device__ float d_part[64 * 256];
__device__ float d_cvec[256];
// fragment-ordered bf16 weights: [mat][kt(16)][nt(32)][lane(32)][reg(2)] u32
__device__ __align__(16) u32 d_BfragH[4 * 32768];
__device__ __align__(16) u32 d_BfragL[4 * 32768];

// ---------------- helpers ---------------------------------------------------
__device__ __forceinline__ float4 f4add(float4 a, float4 b) {
    return make_float4(a.x + b.x, a.y + b.y, a.z + b.z, a.w + b.w);
}
__device__ __forceinline__ u32 pack_bf2(float lo, float hi) {
    __nv_bfloat16 a = __float2bfloat16(lo), b = __float2bfloat16(hi);
    return ((u32)__bfloat16_as_ushort(b) << 16) | __bfloat16_as_ushort(a);
}
__device__ __forceinline__ void mma16816(float* c, const u32* a, const u32* b) {
    asm volatile(
        "mma.sync.aligned.m16n8k16.row.col.f32.bf16.bf16.f32 "
        "{%0,%1,%2,%3}, {%4,%5,%6,%7}, {%8,%9}, {%0,%1,%2,%3};"
        : "+f"(c[0]), "+f"(c[1]), "+f"(c[2]), "+f"(c[3])
        : "r"(a[0]), "r"(a[1]), "r"(a[2]), "r"(a[3]), "r"(b[0]), "r"(b[1]));
}

// ---------------- small kernels ---------------------------------------------
__global__ void k_init() {
    int i = blockIdx.x * 256 + threadIdx.x;
    if (i < NMAPC) d_owner[i] = -1;
}
__global__ void k_setowner(const int* __restrict__ key_ids) {
    int b = blockIdx.x * 256 + threadIdx.x;
    if (b < BB) {
        const int* kd = key_ids + b * 6;
        int idx = kd[0]*3125 + kd[1]*625 + kd[2]*125 + kd[3]*25 + kd[4]*5 + kd[5];
        d_owner[idx] = b;
    }
}
// EW = emb @ sage_W[0]   (6x256 @ 256x256)
__global__ void k_prepEW(const float* __restrict__ emb, const float* __restrict__ W0) {
    __shared__ float er[256];
    int e = blockIdx.x, c = threadIdx.x;
    er[c] = emb[e * 256 + c];
    __syncthreads();
    float acc = 0.f;
    for (int k = 0; k < 256; k++) acc = fmaf(er[k], W0[k * 256 + c], acc);
    d_EW[e * 256 + c] = acc;
}
// layer 1 = gather-add of EW rows + bias -> LN -> ReLU   (warp per row)
__global__ void k_layer1(const int* __restrict__ features,
                         const float* __restrict__ bias,
                         const float* __restrict__ gamma,
                         const float* __restrict__ beta) {
    int warp = threadIdx.x >> 5, lane = threadIdx.x & 31;
    int m = blockIdx.x * 8 + warp;          // < 24576
    int b = m / 3, j = m - 3 * b;
    const int* f = features + b * 9;
    int lo = (j == 0) ? 0 : (j - 1);
    bool three = (j != 0);
    float scl = three ? (1.f / 3.f) : 0.5f;
    const float* e0 = d_EW + f[lo] * 256;
    const float* e1 = d_EW + f[lo + 1] * 256;
    const float* e2 = three ? (d_EW + f[lo + 2] * 256) : e1;
    float v[8], s = 0.f, q = 0.f;
#pragma unroll
    for (int i = 0; i < 8; i++) {
        int c = lane + 32 * i;
        float x = e0[c] + e1[c];
        if (three) x += e2[c];
        x = x * scl + bias[c];
        v[i] = x; s += x; q += x * x;
    }
#pragma unroll
    for (int o = 16; o > 0; o >>= 1) {
        s += __shfl_xor_sync(0xffffffffu, s, o);
        q += __shfl_xor_sync(0xffffffffu, q, o);
    }
    float mean = s * (1.f / 256.f);
    float var  = q * (1.f / 256.f) - mean * mean;
    float rsd  = rsqrtf(var + 1e-5f);
#pragma unroll
    for (int i = 0; i < 8; i++) {
        int c = lane + 32 * i;
        d_h1[(size_t)m * 256 + c] = fmaxf((v[i] - mean) * rsd * gamma[c] + beta[c], 0.f);
    }
}
// W -> bf16 hi/lo fragment images (mma m16n8k16 B-layout, per-lane order)
__global__ void k_prepW(const float* __restrict__ sage_W, const float* __restrict__ pW1) {
    int t = blockIdx.x * 256 + threadIdx.x;   // 98304 threads: mats 1..3
    int rg  = t & 1;
    int l   = (t >> 1) & 31;
    int nt  = (t >> 6) & 31;
    int kt  = (t >> 11) & 15;
    int mat = (t >> 15) + 1;                  // 1..3
    const float* src = (mat < 3) ? (sage_W + (size_t)mat * 65536) : pW1;
    int n  = nt * 8 + (l >> 2);
    int k0 = kt * 16 + (l & 3) * 2 + rg * 8;
    float x0 = src[(size_t)k0 * 256 + n];
    float x1 = src[(size_t)(k0 + 1) * 256 + n];
    __nv_bfloat16 h0 = __float2bfloat16(x0), h1 = __float2bfloat16(x1);
    float l0 = x0 - __bfloat162float(h0), l1 = x1 - __bfloat162float(h1);
    int di = mat * 32768 + ((kt * 32 + nt) * 32 + l) * 2 + rg;
    d_BfragH[di] = ((u32)__bfloat16_as_ushort(h1) << 16) | __bfloat16_as_ushort(h0);
    d_BfragL[di] = pack_bf2(l0, l1);
}

// ---------------- fused HMMA GEMM -------------------------------------------
// CTA: 64 rows x 256 cols. 8 warps = 2(M) x 4(N), warp tile 32x64.
#define AH_OFF 0
#define AL_OFF 33792
#define SS_OFF 67584
#define SMEM_D (67584 + 2048 + 512)

template<int MODE>
__global__ __launch_bounds__(256) void gemm_fused(
    int mat,
    const float* __restrict__ bias, const float* __restrict__ gamma, const float* __restrict__ beta,
    const float* __restrict__ w2, const float* __restrict__ w2b,
    float* __restrict__ outp)
{
    extern __shared__ __align__(16) char smem[];
    u32* ah32 = (u32*)(smem + AH_OFF);          // [64][264] bf16 viewed as u32 pairs
    u32* al32 = (u32*)(smem + AL_OFF);
    float* ssum  = (float*)(smem + SS_OFF);     // [4][64]
    float* ssq   = ssum + 256;                  // [4][64]
    float* meanv = ssq + 256;                   // [64]
    float* rsdv  = meanv + 64;                  // [64]

    const int tid = threadIdx.x, lane = tid & 31, warp = tid >> 5;
    const int wm = warp >> 2, wn = warp & 3;
    const int m0 = blockIdx.x * 64;

    // ---- A prologue: aggregate fp32, split hi/lo bf16, stage in smem
    {
        int row = tid >> 2, cb = (tid & 3) * 64;
        int m = m0 + row;
        const float* s0; const float* s1 = nullptr; const float* s2 = nullptr;
        float scl = 1.f;
        if (MODE == 2) {
            const float* base = d_h1 + (size_t)(m >> 1) * 768;
            s0 = base; s1 = base + 256;
            if (m & 1) s2 = base + 512;
            scl = (m & 1) ? (1.f / 3.f) : 0.5f;
        } else if (MODE == 3) {
            const float* base = d_h2 + (size_t)m * 512;
            s0 = base; s1 = base + 256; scl = 0.5f;
        } else {
            s0 = d_g + (size_t)m * 256;
        }
#pragma unroll
        for (int i = 0; i < 16; i++) {
            float4 a = *(const float4*)&s0[cb + 4 * i];
            if (MODE != 4) {
                a = f4add(a, *(const float4*)&s1[cb + 4 * i]);
                if (s2) a = f4add(a, *(const float4*)&s2[cb + 4 * i]);
                a.x *= scl; a.y *= scl; a.z *= scl; a.w *= scl;
            }
            __nv_bfloat16 hx = __float2bfloat16(a.x), hy = __float2bfloat16(a.y);
            __nv_bfloat16 hz = __float2bfloat16(a.z), hw = __float2bfloat16(a.w);
            int off = row * 264 + cb + 4 * i;      // bf16 offset, even
            ah32[(off >> 1)]     = ((u32)__bfloat16_as_ushort(hy) << 16) | __bfloat16_as_ushort(hx);
            ah32[(off >> 1) + 1] = ((u32)__bfloat16_as_ushort(hw) << 16) | __bfloat16_as_ushort(hz);
            al32[(off >> 1)]     = pack_bf2(a.x - __bfloat162float(hx), a.y - __bfloat162float(hy));
            al32[(off >> 1) + 1] = pack_bf2(a.z - __bfloat162float(hz), a.w - __bfloat162float(hw));
        }
    }
    __syncthreads();

    // ---- main loop with 1-deep register prefetch of B fragments
    float acc[2][8][4];
#pragma unroll
    for (int mt = 0; mt < 2; mt++)
#pragma unroll
        for (int nt = 0; nt < 8; nt++)
#pragma unroll
            for (int q = 0; q < 4; q++) acc[mt][nt][q] = 0.f;

    const int bbase = mat * 32768 + ((wn * 8) * 32 + lane) * 2;   // + kt*2048 + nt*64
    const u32* BH = d_BfragH + bbase;
    const u32* BL = d_BfragL + bbase;
    const int arow = wm * 32 + (lane >> 2);

    u32 bh[2][8][2], bl[2][8][2];
#pragma unroll
    for (int nt = 0; nt < 8; nt++) {
        uint2 vh = *(const uint2*)&BH[nt * 64];
        uint2 vl = *(const uint2*)&BL[nt * 64];
        bh[0][nt][0] = vh.x; bh[0][nt][1] = vh.y;
        bl[0][nt][0] = vl.x; bl[0][nt][1] = vl.y;
    }

#pragma unroll
    for (int kt = 0; kt < 16; kt++) {
        const int cur = kt & 1, nxt = cur ^ 1;
        if (kt < 15) {
            int o = (kt + 1) * 2048;
#pragma unroll
            for (int nt = 0; nt < 8; nt++) {
                uint2 vh = *(const uint2*)&BH[o + nt * 64];
                bh[nxt][nt][0] = vh.x; bh[nxt][nt][1] = vh.y;
            }
#pragma unroll
            for (int nt = 0; nt < 8; nt++) {
                uint2 vl = *(const uint2*)&BL[o + nt * 64];
                bl[nxt][nt][0] = vl.x; bl[nxt][nt][1] = vl.y;
            }
        }
        u32 ah[2][4], al[2][4];
        int acol = kt * 16 + (lane & 3) * 2;
#pragma unroll
        for (int mt = 0; mt < 2; mt++) {
            int base = (arow + mt * 16) * 264 + acol;   // bf16 offset (even)
            ah[mt][0] = ah32[(base) >> 1];
            ah[mt][1] = ah32[(base + 8 * 264) >> 1];
            ah[mt][2] = ah32[(base + 8) >> 1];
            ah[mt][3] = ah32[(base + 8 * 264 + 8) >> 1];
            al[mt][0] = al32[(base) >> 1];
            al[mt][1] = al32[(base + 8 * 264) >> 1];
            al[mt][2] = al32[(base + 8) >> 1];
            al[mt][3] = al32[(base + 8 * 264 + 8) >> 1];
        }
#pragma unroll
        for (int mt = 0; mt < 2; mt++)
#pragma unroll
            for (int nt = 0; nt < 8; nt++)
                mma16816(acc[mt][nt], ah[mt], bh[cur][nt]);
#pragma unroll
        for (int mt = 0; mt < 2; mt++)
#pragma unroll
            for (int nt = 0; nt < 8; nt++)
                mma16816(acc[mt][nt], al[mt], bh[cur][nt]);
#pragma unroll
        for (int mt = 0; mt < 2; mt++)
#pragma unroll
            for (int nt = 0; nt < 8; nt++)
                mma16816(acc[mt][nt], ah[mt], bl[cur][nt]);
    }

    // ---- epilogue
    if (MODE <= 3) {
        float bv[8][2];
#pragma unroll
        for (int nt = 0; nt < 8; nt++) {
            int c = wn * 64 + nt * 8 + (lane & 3) * 2;
            bv[nt][0] = bias[c]; bv[nt][1] = bias[c + 1];
        }
#pragma unroll
        for (int mt = 0; mt < 2; mt++) {
            float sL = 0.f, qL = 0.f, sH = 0.f, qH = 0.f;
#pragma unroll
            for (int nt = 0; nt < 8; nt++) {
                float v0 = acc[mt][nt][0] + bv[nt][0], v1 = acc[mt][nt][1] + bv[nt][1];
                float v2 = acc[mt][nt][2] + bv[nt][0], v3 = acc[mt][nt][3] + bv[nt][1];
                sL += v0 + v1; qL += v0 * v0 + v1 * v1;
                sH += v2 + v3; qH += v2 * v2 + v3 * v3;
            }
#pragma unroll
            for (int o = 1; o <= 2; o <<= 1) {
                sL += __shfl_xor_sync(0xffffffffu, sL, o);
                qL += __shfl_xor_sync(0xffffffffu, qL, o);
                sH += __shfl_xor_sync(0xffffffffu, sH, o);
                qH += __shfl_xor_sync(0xffffffffu, qH, o);
            }
            if ((lane & 3) == 0) {
                int r = wm * 32 + mt * 16 + (lane >> 2);
                ssum[wn * 64 + r] = sL;     ssq[wn * 64 + r] = qL;
                ssum[wn * 64 + r + 8] = sH; ssq[wn * 64 + r + 8] = qH;
            }
        }
        __syncthreads();
        if (tid < 64) {
            float s  = ssum[tid] + ssum[64 + tid] + ssum[128 + tid] + ssum[192 + tid];
            float q  = ssq[tid]  + ssq[64 + tid]  + ssq[128 + tid]  + ssq[192 + tid];
            float mean = s * (1.f / 256.f);
            float var  = q * (1.f / 256.f) - mean * mean;
            meanv[tid] = mean;
            rsdv[tid]  = rsqrtf(var + 1e-5f);
        }
        __syncthreads();
        float* O = (MODE == 2) ? d_h2 : d_g;
#pragma unroll
        for (int mt = 0; mt < 2; mt++) {
            int r = wm * 32 + mt * 16 + (lane >> 2);
            float mn0 = meanv[r], rs0 = rsdv[r];
            float mn1 = meanv[r + 8], rs1 = rsdv[r + 8];
#pragma unroll
            for (int nt = 0; nt < 8; nt++) {
                int c = wn * 64 + nt * 8 + (lane & 3) * 2;
                float g0 = gamma[c], g1 = gamma[c + 1];
                float b0 = beta[c],  b1 = beta[c + 1];
                float v0 = acc[mt][nt][0] + bv[nt][0], v1 = acc[mt][nt][1] + bv[nt][1];
                float v2 = acc[mt][nt][2] + bv[nt][0], v3 = acc[mt][nt][3] + bv[nt][1];
                float2 oL = make_float2(fmaxf((v0 - mn0) * rs0 * g0 + b0, 0.f),
                                        fmaxf((v1 - mn0) * rs0 * g1 + b1, 0.f));
                float2 oH = make_float2(fmaxf((v2 - mn1) * rs1 * g0 + b0, 0.f),
                                        fmaxf((v3 - mn1) * rs1 * g1 + b1, 0.f));
                *(float2*)&O[(size_t)(m0 + r) * 256 + c]     = oL;
                *(float2*)&O[(size_t)(m0 + r + 8) * 256 + c] = oH;
            }
        }
    } else {
        float cv[8][2], wv[8][2];
#pragma unroll
        for (int nt = 0; nt < 8; nt++) {
            int c = wn * 64 + nt * 8 + (lane & 3) * 2;
            cv[nt][0] = d_cvec[c]; cv[nt][1] = d_cvec[c + 1];
            wv[nt][0] = w2[c];     wv[nt][1] = w2[c + 1];
        }
#pragma unroll
        for (int mt = 0; mt < 2; mt++) {
            float pL = 0.f, pH = 0.f;
#pragma unroll
            for (int nt = 0; nt < 8; nt++) {
                pL = fmaf(fmaxf(acc[mt][nt][0] + cv[nt][0], 0.f), wv[nt][0], pL);
                pL = fmaf(fmaxf(acc[mt][nt][1] + cv[nt][1], 0.f), wv[nt][1], pL);
                pH = fmaf(fmaxf(acc[mt][nt][2] + cv[nt][0], 0.f), wv[nt][0], pH);
                pH = fmaf(fmaxf(acc[mt][nt][3] + cv[nt][1], 0.f), wv[nt][1], pH);
            }
#pragma unroll
            for (int o = 1; o <= 2; o <<= 1) {
                pL += __shfl_xor_sync(0xffffffffu, pL, o);
                pH += __shfl_xor_sync(0xffffffffu, pH, o);
            }
            if ((lane & 3) == 0) {
                int r = wm * 32 + mt * 16 + (lane >> 2);
                ssum[wn * 64 + r] = pL;
                ssum[wn * 64 + r + 8] = pH;
            }
        }
        __syncthreads();
        if (tid < 64)
            outp[m0 + tid] = ssum[tid] + ssum[64 + tid] + ssum[128 + tid] + ssum[192 + tid]
                           + w2b[0];
    }
}

// ---------------- dnn-device graph (tiny, fp32) -----------------------------
__global__ void k_accum(const int* __restrict__ dd_src) {
    int c = threadIdx.x;
    int e0 = blockIdx.x * 32;
    float loc = 0.f;
    for (int i = 0; i < 32; i++) {
        int o = d_owner[dd_src[e0 + i]];
        if (o >= 0) loc += d_g[(size_t)o * 256 + c];
    }
    d_part[blockIdx.x * 256 + c] = loc;
}

__global__ void k_device(const float* __restrict__ aug,  const float* __restrict__ infoW,
                         const float* __restrict__ infob,
                         const float* __restrict__ ddW,  const float* __restrict__ ddb,
                         const float* __restrict__ ng,   const float* __restrict__ nb,
                         const float* __restrict__ pW1,  const float* __restrict__ pb1) {
    __shared__ float t[256], dev[256], rsum[8], rssq[8];
    int c = threadIdx.x, lane = c & 31, warp = c >> 5;

    float agg = 0.f;
    for (int i = 0; i < 64; i++) agg += d_part[i * 256 + c];

    float info = infob[c];
#pragma unroll
    for (int j = 0; j < 5; j++) info = fmaf(aug[j], infoW[j * 256 + c], info);

    t[c] = (agg + info) * (1.f / 2049.f);
    __syncthreads();

    float acc = ddb[c];
    for (int k = 0; k < 256; k++) acc = fmaf(t[k], ddW[k * 256 + c], acc);

    float s = acc, ss = acc * acc;
#pragma unroll
    for (int o = 16; o > 0; o >>= 1) {
        s  += __shfl_xor_sync(0xffffffffu, s, o);
        ss += __shfl_xor_sync(0xffffffffu, ss, o);
    }
    if (lane == 0) { rsum[warp] = s; rssq[warp] = ss; }
    __syncthreads();
    if (c == 0) {
        float S = 0.f, SS = 0.f;
        for (int i = 0; i < 8; i++) { S += rsum[i]; SS += rssq[i]; }
        rsum[0] = S; rssq[0] = SS;
    }
    __syncthreads();
    float mean = rsum[0] * (1.f / 256.f);
    float var  = rssq[0] * (1.f / 256.f) - mean * mean;
    float rsd  = rsqrtf(var + 1e-5f);
    dev[c] = fmaxf((acc - mean) * rsd * ng[c] + nb[c], 0.f);
    __syncthreads();

    float cv = pb1[c];
    for (int k = 0; k < 256; k++) cv = fmaf(dev[k], pW1[(size_t)(256 + k) * 256 + c], cv);
    d_cvec[c] = cv;
}

// ---------------- launch ----------------------------------------------------
extern "C" void kernel_launch(void* const* d_in, const int* in_sizes, int n_in,
                              void* d_out, int out_size) {
    const int*   features = (const int*)  d_in[0];
    const int*   key_ids  = (const int*)  d_in[1];
    const int*   dd_src   = (const int*)  d_in[4];
    const float* emb      = (const float*)d_in[5];
    const float* sage_W   = (const float*)d_in[6];
    const float* sage_b   = (const float*)d_in[7];
    const float* ln_g     = (const float*)d_in[8];
    const float* ln_b     = (const float*)d_in[9];
    const float* dd_W     = (const float*)d_in[10];
    const float* dd_b     = (const float*)d_in[11];
    const float* norm_g   = (const float*)d_in[12];
    const float* norm_b   = (const float*)d_in[13];
    const float* info_W   = (const float*)d_in[14];
    const float* info_b   = (const float*)d_in[15];
    const float* aug      = (const float*)d_in[16];
    const float* pW1      = (const float*)d_in[17];
    const float* pb1      = (const float*)d_in[18];
    const float* pW2      = (const float*)d_in[19];
    const float* pb2      = (const float*)d_in[20];
    float* out = (float*)d_out;

    static bool attr_done = false;
    if (!attr_done) {
        cudaFuncSetAttribute(gemm_fused<2>, cudaFuncAttributeMaxDynamicSharedMemorySize, SMEM_D);
        cudaFuncSetAttribute(gemm_fused<3>, cudaFuncAttributeMaxDynamicSharedMemorySize, SMEM_D);
        cudaFuncSetAttribute(gemm_fused<4>, cudaFuncAttributeMaxDynamicSharedMemorySize, SMEM_D);
        attr_done = true;
    }

    k_init<<<(NMAPC + 255) / 256, 256>>>();
    k_setowner<<<BB / 256, 256>>>(key_ids);
    k_prepW<<<384, 256>>>(sage_W, pW1);
    k_prepEW<<<6, 256>>>(emb, sage_W);

    // layer 1: exact fp32 via EW gather (no GEMM)
    k_layer1<<<3 * BB / 8, 256>>>(features, sage_b, ln_g, ln_b);

    gemm_fused<2><<<256, 256, SMEM_D>>>(1, sage_b + 256, ln_g + 256, ln_b + 256,
                                        nullptr, nullptr, nullptr);
    gemm_fused<3><<<128, 256, SMEM_D>>>(2, sage_b + 512, ln_g + 512, ln_b + 512,
                                        nullptr, nullptr, nullptr);

    k_accum<<<64, 256>>>(dd_src);
    k_device<<<1, 256>>>(aug, info_W, info_b, dd_W, dd_b, norm_g, norm_b, pW1, pb1);

    gemm_fused<4><<<128, 256, SMEM_D>>>(3, nullptr, nullptr, nullptr,
                                        pW2, pb2, out);
}

// round 14
// speedup vs baseline: 1.4022x; 1.0076x over previous
#include <cuda_runtime.h>
#include <cuda_bf16.h>

#define BB 8192
#define NMAPC 15625
typedef unsigned int u32;

// ---------------- scratch (static device globals: allocation-free) ----------
__device__ int   d_owner[NMAPC];
__device__ float d_EWp[48 * 256];             // partial emb @ W0 (8 k-chunks)
__device__ float d_EW[6 * 256];               // emb @ sage_W[0]
__device__ float d_h1[(size_t)BB * 3 * 256];
__device__ float d_h2[(size_t)BB * 2 * 256];
__device__ float d_g [(size_t)BB * 256];
__device__ float d_part[64 * 256];
__device__ float d_cvec[256];
// fragment-ordered bf16 weights: [mat][kt(16)][nt(32)][lane(32)][reg(2)] u32
__device__ __align__(16) u32 d_BfragH[4 * 32768];
__device__ __align__(16) u32 d_BfragL[4 * 32768];

// ---------------- helpers ---------------------------------------------------
__device__ __forceinline__ float4 f4add(float4 a, float4 b) {
    return make_float4(a.x + b.x, a.y + b.y, a.z + b.z, a.w + b.w);
}
__device__ __forceinline__ u32 pack_bf2(float lo, float hi) {
    __nv_bfloat16 a = __float2bfloat16(lo), b = __float2bfloat16(hi);
    return ((u32)__bfloat16_as_ushort(b) << 16) | __bfloat16_as_ushort(a);
}
__device__ __forceinline__ void mma16816(float* c, const u32* a, const u32* b) {
    asm volatile(
        "mma.sync.aligned.m16n8k16.row.col.f32.bf16.bf16.f32 "
        "{%0,%1,%2,%3}, {%4,%5,%6,%7}, {%8,%9}, {%0,%1,%2,%3};"
        : "+f"(c[0]), "+f"(c[1]), "+f"(c[2]), "+f"(c[3])
        : "r"(a[0]), "r"(a[1]), "r"(a[2]), "r"(a[3]), "r"(b[0]), "r"(b[1]));
}

// ---------------- small kernels ---------------------------------------------
__global__ void k_init() {
    int i = blockIdx.x * 256 + threadIdx.x;
    if (i < NMAPC) d_owner[i] = -1;
}
__global__ void k_setowner(const int* __restrict__ key_ids) {
    int b = blockIdx.x * 256 + threadIdx.x;
    if (b < BB) {
        const int* kd = key_ids + b * 6;
        int idx = kd[0]*3125 + kd[1]*625 + kd[2]*125 + kd[3]*25 + kd[4]*5 + kd[5];
        d_owner[idx] = b;
    }
}
// EW partials: block = (e * 8 + chunk), k-range [chunk*32, chunk*32+32)
__global__ void k_prepEW(const float* __restrict__ emb, const float* __restrict__ W0) {
    __shared__ float er[32];
    int e = blockIdx.x >> 3, ch = blockIdx.x & 7, c = threadIdx.x;
    int k0 = ch * 32;
    if (c < 32) er[c] = emb[e * 256 + k0 + c];
    __syncthreads();
    float acc = 0.f;
#pragma unroll
    for (int k = 0; k < 32; k++) acc = fmaf(er[k], W0[(size_t)(k0 + k) * 256 + c], acc);
    d_EWp[blockIdx.x * 256 + c] = acc;
}
__global__ void k_prepEW2(void) {
    int e = blockIdx.x, c = threadIdx.x;
    float s = 0.f;
#pragma unroll
    for (int ch = 0; ch < 8; ch++) s += d_EWp[(e * 8 + ch) * 256 + c];
    d_EW[e * 256 + c] = s;
}
// layer 1 = gather-add of EW rows + bias -> LN -> ReLU   (warp per row)
__global__ void k_layer1(const int* __restrict__ features,
                         const float* __restrict__ bias,
                         const float* __restrict__ gamma,
                         const float* __restrict__ beta) {
    int warp = threadIdx.x >> 5, lane = threadIdx.x & 31;
    int m = blockIdx.x * 8 + warp;          // < 24576
    int b = m / 3, j = m - 3 * b;
    const int* f = features + b * 9;
    int lo = (j == 0) ? 0 : (j - 1);
    bool three = (j != 0);
    float scl = three ? (1.f / 3.f) : 0.5f;
    const float* e0 = d_EW + f[lo] * 256;
    const float* e1 = d_EW + f[lo + 1] * 256;
    const float* e2 = three ? (d_EW + f[lo + 2] * 256) : e1;
    float v[8], s = 0.f, q = 0.f;
#pragma unroll
    for (int i = 0; i < 8; i++) {
        int c = lane + 32 * i;
        float x = e0[c] + e1[c];
        if (three) x += e2[c];
        x = x * scl + bias[c];
        v[i] = x; s += x; q += x * x;
    }
#pragma unroll
    for (int o = 16; o > 0; o >>= 1) {
        s += __shfl_xor_sync(0xffffffffu, s, o);
        q += __shfl_xor_sync(0xffffffffu, q, o);
    }
    float mean = s * (1.f / 256.f);
    float var  = q * (1.f / 256.f) - mean * mean;
    float rsd  = rsqrtf(var + 1e-5f);
#pragma unroll
    for (int i = 0; i < 8; i++) {
        int c = lane + 32 * i;
        d_h1[(size_t)m * 256 + c] = fmaxf((v[i] - mean) * rsd * gamma[c] + beta[c], 0.f);
    }
}
// W -> bf16 hi/lo fragment images (mma m16n8k16 B-layout, per-lane order)
__global__ void k_prepW(const float* __restrict__ sage_W, const float* __restrict__ pW1) {
    int t = blockIdx.x * 256 + threadIdx.x;   // 98304 threads: mats 1..3
    int rg  = t & 1;
    int l   = (t >> 1) & 31;
    int nt  = (t >> 6) & 31;
    int kt  = (t >> 11) & 15;
    int mat = (t >> 15) + 1;                  // 1..3
    const float* src = (mat < 3) ? (sage_W + (size_t)mat * 65536) : pW1;
    int n  = nt * 8 + (l >> 2);
    int k0 = kt * 16 + (l & 3) * 2 + rg * 8;
    float x0 = src[(size_t)k0 * 256 + n];
    float x1 = src[(size_t)(k0 + 1) * 256 + n];
    __nv_bfloat16 h0 = __float2bfloat16(x0), h1 = __float2bfloat16(x1);
    float l0 = x0 - __bfloat162float(h0), l1 = x1 - __bfloat162float(h1);
    int di = mat * 32768 + ((kt * 32 + nt) * 32 + l) * 2 + rg;
    d_BfragH[di] = ((u32)__bfloat16_as_ushort(h1) << 16) | __bfloat16_as_ushort(h0);
    d_BfragL[di] = pack_bf2(l0, l1);
}

// ---------------- fused HMMA GEMM -------------------------------------------
// CTA: 64 rows x 256 cols. 8 warps = 2(M) x 4(N), warp tile 32x64.
#define AH_OFF 0
#define AL_OFF 33792
#define SS_OFF 67584
#define SMEM_D (67584 + 2048 + 512)

template<int MODE>
__global__ __launch_bounds__(256) void gemm_fused(
    int mat,
    const float* __restrict__ bias, const float* __restrict__ gamma, const float* __restrict__ beta,
    const float* __restrict__ w2, const float* __restrict__ w2b,
    float* __restrict__ outp)
{
    extern __shared__ __align__(16) char smem[];
    u32* ah32 = (u32*)(smem + AH_OFF);          // [64][264] bf16 viewed as u32 pairs
    u32* al32 = (u32*)(smem + AL_OFF);
    float* ssum  = (float*)(smem + SS_OFF);     // [4][64]
    float* ssq   = ssum + 256;                  // [4][64]
    float* meanv = ssq + 256;                   // [64]
    float* rsdv  = meanv + 64;                  // [64]

    const int tid = threadIdx.x, lane = tid & 31, warp = tid >> 5;
    const int wm = warp >> 2, wn = warp & 3;
    const int m0 = blockIdx.x * 64;

    // ---- A prologue: aggregate fp32, split hi/lo bf16, stage in smem
    {
        int row = tid >> 2, cb = (tid & 3) * 64;
        int m = m0 + row;
        const float* s0; const float* s1 = nullptr; const float* s2 = nullptr;
        float scl = 1.f;
        if (MODE == 2) {
            const float* base = d_h1 + (size_t)(m >> 1) * 768;
            s0 = base; s1 = base + 256;
            if (m & 1) s2 = base + 512;
            scl = (m & 1) ? (1.f / 3.f) : 0.5f;
        } else if (MODE == 3) {
            const float* base = d_h2 + (size_t)m * 512;
            s0 = base; s1 = base + 256; scl = 0.5f;
        } else {
            s0 = d_g + (size_t)m * 256;
        }
#pragma unroll
        for (int i = 0; i < 16; i++) {
            float4 a = *(const float4*)&s0[cb + 4 * i];
            if (MODE != 4) {
                a = f4add(a, *(const float4*)&s1[cb + 4 * i]);
                if (s2) a = f4add(a, *(const float4*)&s2[cb + 4 * i]);
                a.x *= scl; a.y *= scl; a.z *= scl; a.w *= scl;
            }
            __nv_bfloat16 hx = __float2bfloat16(a.x), hy = __float2bfloat16(a.y);
            __nv_bfloat16 hz = __float2bfloat16(a.z), hw = __float2bfloat16(a.w);
            int off = row * 264 + cb + 4 * i;      // bf16 offset, even
            ah32[(off >> 1)]     = ((u32)__bfloat16_as_ushort(hy) << 16) | __bfloat16_as_ushort(hx);
            ah32[(off >> 1) + 1] = ((u32)__bfloat16_as_ushort(hw) << 16) | __bfloat16_as_ushort(hz);
            al32[(off >> 1)]     = pack_bf2(a.x - __bfloat162float(hx), a.y - __bfloat162float(hy));
            al32[(off >> 1) + 1] = pack_bf2(a.z - __bfloat162float(hz), a.w - __bfloat162float(hw));
        }
    }
    __syncthreads();

    // ---- main loop with 1-deep register prefetch of B fragments
    float acc[2][8][4];
#pragma unroll
    for (int mt = 0; mt < 2; mt++)
#pragma unroll
        for (int nt = 0; nt < 8; nt++)
#pragma unroll
            for (int q = 0; q < 4; q++) acc[mt][nt][q] = 0.f;

    const int bbase = mat * 32768 + ((wn * 8) * 32 + lane) * 2;   // + kt*2048 + nt*64
    const u32* BH = d_BfragH + bbase;
    const u32* BL = d_BfragL + bbase;
    const int arow = wm * 32 + (lane >> 2);

    u32 bh[2][8][2], bl[2][8][2];
#pragma unroll
    for (int nt = 0; nt < 8; nt++) {
        uint2 vh = *(const uint2*)&BH[nt * 64];
        uint2 vl = *(const uint2*)&BL[nt * 64];
        bh[0][nt][0] = vh.x; bh[0][nt][1] = vh.y;
        bl[0][nt][0] = vl.x; bl[0][nt][1] = vl.y;
    }

#pragma unroll
    for (int kt = 0; kt < 16; kt++) {
        const int cur = kt & 1, nxt = cur ^ 1;
        if (kt < 15) {
            int o = (kt + 1) * 2048;
#pragma unroll
            for (int nt = 0; nt < 8; nt++) {
                uint2 vh = *(const uint2*)&BH[o + nt * 64];
                bh[nxt][nt][0] = vh.x; bh[nxt][nt][1] = vh.y;
            }
#pragma unroll
            for (int nt = 0; nt < 8; nt++) {
                uint2 vl = *(const uint2*)&BL[o + nt * 64];
                bl[nxt][nt][0] = vl.x; bl[nxt][nt][1] = vl.y;
            }
        }
        u32 ah[2][4], al[2][4];
        int acol = kt * 16 + (lane & 3) * 2;
#pragma unroll
        for (int mt = 0; mt < 2; mt++) {
            int base = (arow + mt * 16) * 264 + acol;   // bf16 offset (even)
            ah[mt][0] = ah32[(base) >> 1];
            ah[mt][1] = ah32[(base + 8 * 264) >> 1];
            ah[mt][2] = ah32[(base + 8) >> 1];
            ah[mt][3] = ah32[(base + 8 * 264 + 8) >> 1];
            al[mt][0] = al32[(base) >> 1];
            al[mt][1] = al32[(base + 8 * 264) >> 1];
            al[mt][2] = al32[(base + 8) >> 1];
            al[mt][3] = al32[(base + 8 * 264 + 8) >> 1];
        }
#pragma unroll
        for (int mt = 0; mt < 2; mt++)
#pragma unroll
            for (int nt = 0; nt < 8; nt++)
                mma16816(acc[mt][nt], ah[mt], bh[cur][nt]);
#pragma unroll
        for (int mt = 0; mt < 2; mt++)
#pragma unroll
            for (int nt = 0; nt < 8; nt++)
                mma16816(acc[mt][nt], al[mt], bh[cur][nt]);
#pragma unroll
        for (int mt = 0; mt < 2; mt++)
#pragma unroll
            for (int nt = 0; nt < 8; nt++)
                mma16816(acc[mt][nt], ah[mt], bl[cur][nt]);
    }

    // ---- epilogue
    if (MODE <= 3) {
        float bv[8][2];
#pragma unroll
        for (int nt = 0; nt < 8; nt++) {
            int c = wn * 64 + nt * 8 + (lane & 3) * 2;
            bv[nt][0] = bias[c]; bv[nt][1] = bias[c + 1];
        }
#pragma unroll
        for (int mt = 0; mt < 2; mt++) {
            float sL = 0.f, qL = 0.f, sH = 0.f, qH = 0.f;
#pragma unroll
            for (int nt = 0; nt < 8; nt++) {
                float v0 = acc[mt][nt][0] + bv[nt][0], v1 = acc[mt][nt][1] + bv[nt][1];
                float v2 = acc[mt][nt][2] + bv[nt][0], v3 = acc[mt][nt][3] + bv[nt][1];
                sL += v0 + v1; qL += v0 * v0 + v1 * v1;
                sH += v2 + v3; qH += v2 * v2 + v3 * v3;
            }
#pragma unroll
            for (int o = 1; o <= 2; o <<= 1) {
                sL += __shfl_xor_sync(0xffffffffu, sL, o);
                qL += __shfl_xor_sync(0xffffffffu, qL, o);
                sH += __shfl_xor_sync(0xffffffffu, sH, o);
                qH += __shfl_xor_sync(0xffffffffu, qH, o);
            }
            if ((lane & 3) == 0) {
                int r = wm * 32 + mt * 16 + (lane >> 2);
                ssum[wn * 64 + r] = sL;     ssq[wn * 64 + r] = qL;
                ssum[wn * 64 + r + 8] = sH; ssq[wn * 64 + r + 8] = qH;
            }
        }
        __syncthreads();
        if (tid < 64) {
            float s  = ssum[tid] + ssum[64 + tid] + ssum[128 + tid] + ssum[192 + tid];
            float q  = ssq[tid]  + ssq[64 + tid]  + ssq[128 + tid]  + ssq[192 + tid];
            float mean = s * (1.f / 256.f);
            float var  = q * (1.f / 256.f) - mean * mean;
            meanv[tid] = mean;
            rsdv[tid]  = rsqrtf(var + 1e-5f);
        }
        __syncthreads();
        float* O = (MODE == 2) ? d_h2 : d_g;
#pragma unroll
        for (int mt = 0; mt < 2; mt++) {
            int r = wm * 32 + mt * 16 + (lane >> 2);
            float mn0 = meanv[r], rs0 = rsdv[r];
            float mn1 = meanv[r + 8], rs1 = rsdv[r + 8];
#pragma unroll
            for (int nt = 0; nt < 8; nt++) {
                int c = wn * 64 + nt * 8 + (lane & 3) * 2;
                float g0 = gamma[c], g1 = gamma[c + 1];
                float b0 = beta[c],  b1 = beta[c + 1];
                float v0 = acc[mt][nt][0] + bv[nt][0], v1 = acc[mt][nt][1] + bv[nt][1];
                float v2 = acc[mt][nt][2] + bv[nt][0], v3 = acc[mt][nt][3] + bv[nt][1];
                float2 oL = make_float2(fmaxf((v0 - mn0) * rs0 * g0 + b0, 0.f),
                                        fmaxf((v1 - mn0) * rs0 * g1 + b1, 0.f));
                float2 oH = make_float2(fmaxf((v2 - mn1) * rs1 * g0 + b0, 0.f),
                                        fmaxf((v3 - mn1) * rs1 * g1 + b1, 0.f));
                *(float2*)&O[(size_t)(m0 + r) * 256 + c]     = oL;
                *(float2*)&O[(size_t)(m0 + r + 8) * 256 + c] = oH;
            }
        }
    } else {
        float cv[8][2], wv[8][2];
#pragma unroll
        for (int nt = 0; nt < 8; nt++) {
            int c = wn * 64 + nt * 8 + (lane & 3) * 2;
            cv[nt][0] = d_cvec[c]; cv[nt][1] = d_cvec[c + 1];
            wv[nt][0] = w2[c];     wv[nt][1] = w2[c + 1];
        }
#pragma unroll
        for (int mt = 0; mt < 2; mt++) {
            float pL = 0.f, pH = 0.f;
#pragma unroll
            for (int nt = 0; nt < 8; nt++) {
                pL = fmaf(fmaxf(acc[mt][nt][0] + cv[nt][0], 0.f), wv[nt][0], pL);
                pL = fmaf(fmaxf(acc[mt][nt][1] + cv[nt][1], 0.f), wv[nt][1], pL);
                pH = fmaf(fmaxf(acc[mt][nt][2] + cv[nt][0], 0.f), wv[nt][0], pH);
                pH = fmaf(fmaxf(acc[mt][nt][3] + cv[nt][1], 0.f), wv[nt][1], pH);
            }
#pragma unroll
            for (int o = 1; o <= 2; o <<= 1) {
                pL += __shfl_xor_sync(0xffffffffu, pL, o);
                pH += __shfl_xor_sync(0xffffffffu, pH, o);
            }
            if ((lane & 3) == 0) {
                int r = wm * 32 + mt * 16 + (lane >> 2);
                ssum[wn * 64 + r] = pL;
                ssum[wn * 64 + r + 8] = pH;
            }
        }
        __syncthreads();
        if (tid < 64)
            outp[m0 + tid] = ssum[tid] + ssum[64 + tid] + ssum[128 + tid] + ssum[192 + tid]
                           + w2b[0];
    }
}

// ---------------- dnn-device graph (tiny, fp32) -----------------------------
__global__ void k_accum(const int* __restrict__ dd_src) {
    int c = threadIdx.x;
    int e0 = blockIdx.x * 32;
    float loc = 0.f;
    for (int i = 0; i < 32; i++) {
        int o = d_owner[dd_src[e0 + i]];
        if (o >= 0) loc += d_g[(size_t)o * 256 + c];
    }
    d_part[blockIdx.x * 256 + c] = loc;
}

__global__ void k_device(const float* __restrict__ aug,  const float* __restrict__ infoW,
                         const float* __restrict__ infob,
                         const float* __restrict__ ddW,  const float* __restrict__ ddb,
                         const float* __restrict__ ng,   const float* __restrict__ nb,
                         const float* __restrict__ pW1,  const float* __restrict__ pb1) {
    __shared__ float t[256], dev[256], rsum[8], rssq[8];
    int c = threadIdx.x, lane = c & 31, warp = c >> 5;

    float agg = 0.f;
    for (int i = 0; i < 64; i++) agg += d_part[i * 256 + c];

    float info = infob[c];
#pragma unroll
    for (int j = 0; j < 5; j++) info = fmaf(aug[j], infoW[j * 256 + c], info);

    t[c] = (agg + info) * (1.f / 2049.f);
    __syncthreads();

    float acc = ddb[c];
    for (int k = 0; k < 256; k++) acc = fmaf(t[k], ddW[k * 256 + c], acc);

    float s = acc, ss = acc * acc;
#pragma unroll
    for (int o = 16; o > 0; o >>= 1) {
        s  += __shfl_xor_sync(0xffffffffu, s, o);
        ss += __shfl_xor_sync(0xffffffffu, ss, o);
    }
    if (lane == 0) { rsum[warp] = s; rssq[warp] = ss; }
    __syncthreads();
    if (c == 0) {
        float S = 0.f, SS = 0.f;
        for (int i = 0; i < 8; i++) { S += rsum[i]; SS += rssq[i]; }
        rsum[0] = S; rssq[0] = SS;
    }
    __syncthreads();
    float mean = rsum[0] * (1.f / 256.f);
    float var  = rssq[0] * (1.f / 256.f) - mean * mean;
    float rsd  = rsqrtf(var + 1e-5f);
    dev[c] = fmaxf((acc - mean) * rsd * ng[c] + nb[c], 0.f);
    __syncthreads();

    float cv = pb1[c];
    for (int k = 0; k < 256; k++) cv = fmaf(dev[k], pW1[(size_t)(256 + k) * 256 + c], cv);
    d_cvec[c] = cv;
}

// ---------------- launch ----------------------------------------------------
extern "C" void kernel_launch(void* const* d_in, const int* in_sizes, int n_in,
                              void* d_out, int out_size) {
    const int*   features = (const int*)  d_in[0];
    const int*   key_ids  = (const int*)  d_in[1];
    const int*   dd_src   = (const int*)  d_in[4];
    const float* emb      = (const float*)d_in[5];
    const float* sage_W   = (const float*)d_in[6];
    const float* sage_b   = (const float*)d_in[7];
    const float* ln_g     = (const float*)d_in[8];
    const float* ln_b     = (const float*)d_in[9];
    const float* dd_W     = (const float*)d_in[10];
    const float* dd_b     = (const float*)d_in[11];
    const float* norm_g   = (const float*)d_in[12];
    const float* norm_b   = (const float*)d_in[13];
    const float* info_W   = (const float*)d_in[14];
    const float* info_b   = (const float*)d_in[15];
    const float* aug      = (const float*)d_in[16];
    const float* pW1      = (const float*)d_in[17];
    const float* pb1      = (const float*)d_in[18];
    const float* pW2      = (const float*)d_in[19];
    const float* pb2      = (const float*)d_in[20];
    float* out = (float*)d_out;

    static bool attr_done = false;
    if (!attr_done) {
        cudaFuncSetAttribute(gemm_fused<2>, cudaFuncAttributeMaxDynamicSharedMemorySize, SMEM_D);
        cudaFuncSetAttribute(gemm_fused<3>, cudaFuncAttributeMaxDynamicSharedMemorySize, SMEM_D);
        cudaFuncSetAttribute(gemm_fused<4>, cudaFuncAttributeMaxDynamicSharedMemorySize, SMEM_D);
        attr_done = true;
    }

    k_init<<<(NMAPC + 255) / 256, 256>>>();
    k_setowner<<<BB / 256, 256>>>(key_ids);
    k_prepW<<<384, 256>>>(sage_W, pW1);
    k_prepEW<<<48, 256>>>(emb, sage_W);
    k_prepEW2<<<6, 256>>>();

    // layer 1: exact fp32 via EW gather (no GEMM)
    k_layer1<<<3 * BB / 8, 256>>>(features, sage_b, ln_g, ln_b);

    gemm_fused<2><<<256, 256, SMEM_D>>>(1, sage_b + 256, ln_g + 256, ln_b + 256,
                                        nullptr, nullptr, nullptr);
    gemm_fused<3><<<128, 256, SMEM_D>>>(2, sage_b + 512, ln_g + 512, ln_b + 512,
                                        nullptr, nullptr, nullptr);

    k_accum<<<64, 256>>>(dd_src);
    k_device<<<1, 256>>>(aug, info_W, info_b, dd_W, dd_b, norm_g, norm_b, pW1, pb1);

    gemm_fused<4><<<128, 256, SMEM_D>>>(3, nullptr, nullptr, nullptr,
                                        pW2, pb2, out);
}

// round 15
// speedup vs baseline: 1.5688x; 1.1188x over previous
#include <cuda_runtime.h>
#include <cuda_fp16.h>

#define BB 8192
#define NMAPC 15625
typedef unsigned int u32;
typedef unsigned short u16;

// ---------------- scratch (static device globals: allocation-free) ----------
__device__ int   d_owner[NMAPC];
__device__ float d_EWp[48 * 256];             // partial emb @ W0 (8 k-chunks)
__device__ float d_EW[6 * 256];               // emb @ sage_W[0]
__device__ float d_h1[(size_t)BB * 3 * 256];
__device__ float d_h2[(size_t)BB * 2 * 256];
__device__ float d_g [(size_t)BB * 256];
__device__ float d_part[64 * 256];
__device__ float d_cvec[256];
// fragment-ordered fp16 weight digits: [mat][kt(16)][nt(32)][lane(32)][reg(2)] u32
__device__ __align__(16) u32 d_BfragH[4 * 32768];
__device__ __align__(16) u32 d_BfragL[4 * 32768];

// ---------------- helpers ---------------------------------------------------
__device__ __forceinline__ float4 f4add(float4 a, float4 b) {
    return make_float4(a.x + b.x, a.y + b.y, a.z + b.z, a.w + b.w);
}
__device__ __forceinline__ u32 pack_hf2(float lo, float hi) {
    __half a = __float2half_rn(lo), b = __float2half_rn(hi);
    return ((u32)__half_as_ushort(b) << 16) | __half_as_ushort(a);
}
__device__ __forceinline__ void mma16816(float* c, const u32* a, const u32* b) {
    asm volatile(
        "mma.sync.aligned.m16n8k16.row.col.f32.f16.f16.f32 "
        "{%0,%1,%2,%3}, {%4,%5,%6,%7}, {%8,%9}, {%0,%1,%2,%3};"
        : "+f"(c[0]), "+f"(c[1]), "+f"(c[2]), "+f"(c[3])
        : "r"(a[0]), "r"(a[1]), "r"(a[2]), "r"(a[3]), "r"(b[0]), "r"(b[1]));
}

// ---------------- small kernels ---------------------------------------------
__global__ void k_init() {
    int i = blockIdx.x * 256 + threadIdx.x;
    if (i < NMAPC) d_owner[i] = -1;
}
__global__ void k_setowner(const int* __restrict__ key_ids) {
    int b = blockIdx.x * 256 + threadIdx.x;
    if (b < BB) {
        const int* kd = key_ids + b * 6;
        int idx = kd[0]*3125 + kd[1]*625 + kd[2]*125 + kd[3]*25 + kd[4]*5 + kd[5];
        d_owner[idx] = b;
    }
}
// EW partials: block = (e * 8 + chunk), k-range [chunk*32, chunk*32+32)
__global__ void k_prepEW(const float* __restrict__ emb, const float* __restrict__ W0) {
    __shared__ float er[32];
    int e = blockIdx.x >> 3, ch = blockIdx.x & 7, c = threadIdx.x;
    int k0 = ch * 32;
    if (c < 32) er[c] = emb[e * 256 + k0 + c];
    __syncthreads();
    float acc = 0.f;
#pragma unroll
    for (int k = 0; k < 32; k++) acc = fmaf(er[k], W0[(size_t)(k0 + k) * 256 + c], acc);
    d_EWp[blockIdx.x * 256 + c] = acc;
}
__global__ void k_prepEW2(void) {
    int e = blockIdx.x, c = threadIdx.x;
    float s = 0.f;
#pragma unroll
    for (int ch = 0; ch < 8; ch++) s += d_EWp[(e * 8 + ch) * 256 + c];
    d_EW[e * 256 + c] = s;
}
// layer 1 = gather-add of EW rows + bias -> LN -> ReLU   (warp per row)
__global__ void k_layer1(const int* __restrict__ features,
                         const float* __restrict__ bias,
                         const float* __restrict__ gamma,
                         const float* __restrict__ beta) {
    int warp = threadIdx.x >> 5, lane = threadIdx.x & 31;
    int m = blockIdx.x * 8 + warp;          // < 24576
    int b = m / 3, j = m - 3 * b;
    const int* f = features + b * 9;
    int lo = (j == 0) ? 0 : (j - 1);
    bool three = (j != 0);
    float scl = three ? (1.f / 3.f) : 0.5f;
    const float* e0 = d_EW + f[lo] * 256;
    const float* e1 = d_EW + f[lo + 1] * 256;
    const float* e2 = three ? (d_EW + f[lo + 2] * 256) : e1;
    float v[8], s = 0.f, q = 0.f;
#pragma unroll
    for (int i = 0; i < 8; i++) {
        int c = lane + 32 * i;
        float x = e0[c] + e1[c];
        if (three) x += e2[c];
        x = x * scl + bias[c];
        v[i] = x; s += x; q += x * x;
    }
#pragma unroll
    for (int o = 16; o > 0; o >>= 1) {
        s += __shfl_xor_sync(0xffffffffu, s, o);
        q += __shfl_xor_sync(0xffffffffu, q, o);
    }
    float mean = s * (1.f / 256.f);
    float var  = q * (1.f / 256.f) - mean * mean;
    float rsd  = rsqrtf(var + 1e-5f);
#pragma unroll
    for (int i = 0; i < 8; i++) {
        int c = lane + 32 * i;
        d_h1[(size_t)m * 256 + c] = fmaxf((v[i] - mean) * rsd * gamma[c] + beta[c], 0.f);
    }
}
// W -> fp16 hi/lo digit fragment images (mma m16n8k16 B-layout, per-lane order)
__global__ void k_prepW(const float* __restrict__ sage_W, const float* __restrict__ pW1) {
    int t = blockIdx.x * 256 + threadIdx.x;   // 98304 threads: mats 1..3
    int rg  = t & 1;
    int l   = (t >> 1) & 31;
    int nt  = (t >> 6) & 31;
    int kt  = (t >> 11) & 15;
    int mat = (t >> 15) + 1;                  // 1..3
    const float* src = (mat < 3) ? (sage_W + (size_t)mat * 65536) : pW1;
    int n  = nt * 8 + (l >> 2);
    int k0 = kt * 16 + (l & 3) * 2 + rg * 8;
    float x0 = src[(size_t)k0 * 256 + n];
    float x1 = src[(size_t)(k0 + 1) * 256 + n];
    __half h0 = __float2half_rn(x0), h1 = __float2half_rn(x1);
    float l0 = x0 - __half2float(h0), l1 = x1 - __half2float(h1);
    int di = mat * 32768 + ((kt * 32 + nt) * 32 + l) * 2 + rg;
    d_BfragH[di] = ((u32)__half_as_ushort(h1) << 16) | __half_as_ushort(h0);
    d_BfragL[di] = pack_hf2(l0, l1);
}

// ---------------- fused HMMA GEMM (fp16, 2-term: Ah*Wh + Ah*Wl) -------------
// CTA: 64 rows x 256 cols. 8 warps = 2(M) x 4(N), warp tile 32x64.
#define AH_OFF 0
#define SS_OFF 33792
#define SMEM_D (33792 + 2048 + 512)

template<int MODE>
__global__ __launch_bounds__(256) void gemm_fused(
    int mat,
    const float* __restrict__ bias, const float* __restrict__ gamma, const float* __restrict__ beta,
    const float* __restrict__ w2, const float* __restrict__ w2b,
    float* __restrict__ outp)
{
    extern __shared__ __align__(16) char smem[];
    u32* ah32 = (u32*)(smem + AH_OFF);          // [64][264] fp16 viewed as u32 pairs
    float* ssum  = (float*)(smem + SS_OFF);     // [4][64]
    float* ssq   = ssum + 256;                  // [4][64]
    float* meanv = ssq + 256;                   // [64]
    float* rsdv  = meanv + 64;                  // [64]

    const int tid = threadIdx.x, lane = tid & 31, warp = tid >> 5;
    const int wm = warp >> 2, wn = warp & 3;
    const int m0 = blockIdx.x * 64;

    // ---- A prologue: aggregate fp32, convert fp16, stage in smem
    {
        int row = tid >> 2, cb = (tid & 3) * 64;
        int m = m0 + row;
        const float* s0; const float* s1 = nullptr; const float* s2 = nullptr;
        float scl = 1.f;
        if (MODE == 2) {
            const float* base = d_h1 + (size_t)(m >> 1) * 768;
            s0 = base; s1 = base + 256;
            if (m & 1) s2 = base + 512;
            scl = (m & 1) ? (1.f / 3.f) : 0.5f;
        } else if (MODE == 3) {
            const float* base = d_h2 + (size_t)m * 512;
            s0 = base; s1 = base + 256; scl = 0.5f;
        } else {
            s0 = d_g + (size_t)m * 256;
        }
#pragma unroll
        for (int i = 0; i < 16; i++) {
            float4 a = *(const float4*)&s0[cb + 4 * i];
            if (MODE != 4) {
                a = f4add(a, *(const float4*)&s1[cb + 4 * i]);
                if (s2) a = f4add(a, *(const float4*)&s2[cb + 4 * i]);
                a.x *= scl; a.y *= scl; a.z *= scl; a.w *= scl;
            }
            int off = row * 264 + cb + 4 * i;      // fp16 offset, even
            ah32[(off >> 1)]     = pack_hf2(a.x, a.y);
            ah32[(off >> 1) + 1] = pack_hf2(a.z, a.w);
        }
    }
    __syncthreads();

    // ---- main loop with 1-deep register prefetch of B fragments
    float acc[2][8][4];
#pragma unroll
    for (int mt = 0; mt < 2; mt++)
#pragma unroll
        for (int nt = 0; nt < 8; nt++)
#pragma unroll
            for (int q = 0; q < 4; q++) acc[mt][nt][q] = 0.f;

    const int bbase = mat * 32768 + ((wn * 8) * 32 + lane) * 2;   // + kt*2048 + nt*64
    const u32* BH = d_BfragH + bbase;
    const u32* BL = d_BfragL + bbase;
    const int arow = wm * 32 + (lane >> 2);

    u32 bh[2][8][2], bl[2][8][2];
#pragma unroll
    for (int nt = 0; nt < 8; nt++) {
        uint2 vh = *(const uint2*)&BH[nt * 64];
        uint2 vl = *(const uint2*)&BL[nt * 64];
        bh[0][nt][0] = vh.x; bh[0][nt][1] = vh.y;
        bl[0][nt][0] = vl.x; bl[0][nt][1] = vl.y;
    }

#pragma unroll
    for (int kt = 0; kt < 16; kt++) {
        const int cur = kt & 1, nxt = cur ^ 1;
        if (kt < 15) {
            int o = (kt + 1) * 2048;
#pragma unroll
            for (int nt = 0; nt < 8; nt++) {
                uint2 vh = *(const uint2*)&BH[o + nt * 64];
                bh[nxt][nt][0] = vh.x; bh[nxt][nt][1] = vh.y;
            }
#pragma unroll
            for (int nt = 0; nt < 8; nt++) {
                uint2 vl = *(const uint2*)&BL[o + nt * 64];
                bl[nxt][nt][0] = vl.x; bl[nxt][nt][1] = vl.y;
            }
        }
        u32 ah[2][4];
        int acol = kt * 16 + (lane & 3) * 2;
#pragma unroll
        for (int mt = 0; mt < 2; mt++) {
            int base = (arow + mt * 16) * 264 + acol;   // fp16 offset (even)
            ah[mt][0] = ah32[(base) >> 1];
            ah[mt][1] = ah32[(base + 8 * 264) >> 1];
            ah[mt][2] = ah32[(base + 8) >> 1];
            ah[mt][3] = ah32[(base + 8 * 264 + 8) >> 1];
        }
        // 2 passes: Ah*Wh then Ah*Wl
#pragma unroll
        for (int mt = 0; mt < 2; mt++)
#pragma unroll
            for (int nt = 0; nt < 8; nt++)
                mma16816(acc[mt][nt], ah[mt], bh[cur][nt]);
#pragma unroll
        for (int mt = 0; mt < 2; mt++)
#pragma unroll
            for (int nt = 0; nt < 8; nt++)
                mma16816(acc[mt][nt], ah[mt], bl[cur][nt]);
    }

    // ---- epilogue
    if (MODE <= 3) {
        float bv[8][2];
#pragma unroll
        for (int nt = 0; nt < 8; nt++) {
            int c = wn * 64 + nt * 8 + (lane & 3) * 2;
            bv[nt][0] = bias[c]; bv[nt][1] = bias[c + 1];
        }
#pragma unroll
        for (int mt = 0; mt < 2; mt++) {
            float sL = 0.f, qL = 0.f, sH = 0.f, qH = 0.f;
#pragma unroll
            for (int nt = 0; nt < 8; nt++) {
                float v0 = acc[mt][nt][0] + bv[nt][0], v1 = acc[mt][nt][1] + bv[nt][1];
                float v2 = acc[mt][nt][2] + bv[nt][0], v3 = acc[mt][nt][3] + bv[nt][1];
                sL += v0 + v1; qL += v0 * v0 + v1 * v1;
                sH += v2 + v3; qH += v2 * v2 + v3 * v3;
            }
#pragma unroll
            for (int o = 1; o <= 2; o <<= 1) {
                sL += __shfl_xor_sync(0xffffffffu, sL, o);
                qL += __shfl_xor_sync(0xffffffffu, qL, o);
                sH += __shfl_xor_sync(0xffffffffu, sH, o);
                qH += __shfl_xor_sync(0xffffffffu, qH, o);
            }
            if ((lane & 3) == 0) {
                int r = wm * 32 + mt * 16 + (lane >> 2);
                ssum[wn * 64 + r] = sL;     ssq[wn * 64 + r] = qL;
                ssum[wn * 64 + r + 8] = sH; ssq[wn * 64 + r + 8] = qH;
            }
        }
        __syncthreads();
        if (tid < 64) {
            float s  = ssum[tid] + ssum[64 + tid] + ssum[128 + tid] + ssum[192 + tid];
            float q  = ssq[tid]  + ssq[64 + tid]  + ssq[128 + tid]  + ssq[192 + tid];
            float mean = s * (1.f / 256.f);
            float var  = q * (1.f / 256.f) - mean * mean;
            meanv[tid] = mean;
            rsdv[tid]  = rsqrtf(var + 1e-5f);
        }
        __syncthreads();
        float* O = (MODE == 2) ? d_h2 : d_g;
#pragma unroll
        for (int mt = 0; mt < 2; mt++) {
            int r = wm * 32 + mt * 16 + (lane >> 2);
            float mn0 = meanv[r], rs0 = rsdv[r];
            float mn1 = meanv[r + 8], rs1 = rsdv[r + 8];
#pragma unroll
            for (int nt = 0; nt < 8; nt++) {
                int c = wn * 64 + nt * 8 + (lane & 3) * 2;
                float g0 = gamma[c], g1 = gamma[c + 1];
                float b0 = beta[c],  b1 = beta[c + 1];
                float v0 = acc[mt][nt][0] + bv[nt][0], v1 = acc[mt][nt][1] + bv[nt][1];
                float v2 = acc[mt][nt][2] + bv[nt][0], v3 = acc[mt][nt][3] + bv[nt][1];
                float2 oL = make_float2(fmaxf((v0 - mn0) * rs0 * g0 + b0, 0.f),
                                        fmaxf((v1 - mn0) * rs0 * g1 + b1, 0.f));
                float2 oH = make_float2(fmaxf((v2 - mn1) * rs1 * g0 + b0, 0.f),
                                        fmaxf((v3 - mn1) * rs1 * g1 + b1, 0.f));
                *(float2*)&O[(size_t)(m0 + r) * 256 + c]     = oL;
                *(float2*)&O[(size_t)(m0 + r + 8) * 256 + c] = oH;
            }
        }
    } else {
        float cv[8][2], wv[8][2];
#pragma unroll
        for (int nt = 0; nt < 8; nt++) {
            int c = wn * 64 + nt * 8 + (lane & 3) * 2;
            cv[nt][0] = d_cvec[c]; cv[nt][1] = d_cvec[c + 1];
            wv[nt][0] = w2[c];     wv[nt][1] = w2[c + 1];
        }
#pragma unroll
        for (int mt = 0; mt < 2; mt++) {
            float pL = 0.f, pH = 0.f;
#pragma unroll
            for (int nt = 0; nt < 8; nt++) {
                pL = fmaf(fmaxf(acc[mt][nt][0] + cv[nt][0], 0.f), wv[nt][0], pL);
                pL = fmaf(fmaxf(acc[mt][nt][1] + cv[nt][1], 0.f), wv[nt][1], pL);
                pH = fmaf(fmaxf(acc[mt][nt][2] + cv[nt][0], 0.f), wv[nt][0], pH);
                pH = fmaf(fmaxf(acc[mt][nt][3] + cv[nt][1], 0.f), wv[nt][1], pH);
            }
#pragma unroll
            for (int o = 1; o <= 2; o <<= 1) {
                pL += __shfl_xor_sync(0xffffffffu, pL, o);
                pH += __shfl_xor_sync(0xffffffffu, pH, o);
            }
            if ((lane & 3) == 0) {
                int r = wm * 32 + mt * 16 + (lane >> 2);
                ssum[wn * 64 + r] = pL;
                ssum[wn * 64 + r + 8] = pH;
            }
        }
        __syncthreads();
        if (tid < 64)
            outp[m0 + tid] = ssum[tid] + ssum[64 + tid] + ssum[128 + tid] + ssum[192 + tid]
                           + w2b[0];
    }
}

// ---------------- dnn-device graph (tiny, fp32) -----------------------------
__global__ void k_accum(const int* __restrict__ dd_src) {
    int c = threadIdx.x;
    int e0 = blockIdx.x * 32;
    float loc = 0.f;
    for (int i = 0; i < 32; i++) {
        int o = d_owner[dd_src[e0 + i]];
        if (o >= 0) loc += d_g[(size_t)o * 256 + c];
    }
    d_part[blockIdx.x * 256 + c] = loc;
}

__global__ void k_device(const float* __restrict__ aug,  const float* __restrict__ infoW,
                         const float* __restrict__ infob,
                         const float* __restrict__ ddW,  const float* __restrict__ ddb,
                         const float* __restrict__ ng,   const float* __restrict__ nb,
                         const float* __restrict__ pW1,  const float* __restrict__ pb1) {
    __shared__ float t[256], dev[256], rsum[8], rssq[8];
    int c = threadIdx.x, lane = c & 31, warp = c >> 5;

    float agg = 0.f;
    for (int i = 0; i < 64; i++) agg += d_part[i * 256 + c];

    float info = infob[c];
#pragma unroll
    for (int j = 0; j < 5; j++) info = fmaf(aug[j], infoW[j * 256 + c], info);

    t[c] = (agg + info) * (1.f / 2049.f);
    __syncthreads();

    float acc = ddb[c];
    for (int k = 0; k < 256; k++) acc = fmaf(t[k], ddW[k * 256 + c], acc);

    float s = acc, ss = acc * acc;
#pragma unroll
    for (int o = 16; o > 0; o >>= 1) {
        s  += __shfl_xor_sync(0xffffffffu, s, o);
        ss += __shfl_xor_sync(0xffffffffu, ss, o);
    }
    if (lane == 0) { rsum[warp] = s; rssq[warp] = ss; }
    __syncthreads();
    if (c == 0) {
        float S = 0.f, SS = 0.f;
        for (int i = 0; i < 8; i++) { S += rsum[i]; SS += rssq[i]; }
        rsum[0] = S; rssq[0] = SS;
    }
    __syncthreads();
    float mean = rsum[0] * (1.f / 256.f);
    float var  = rssq[0] * (1.f / 256.f) - mean * mean;
    float rsd  = rsqrtf(var + 1e-5f);
    dev[c] = fmaxf((acc - mean) * rsd * ng[c] + nb[c], 0.f);
    __syncthreads();

    float cv = pb1[c];
    for (int k = 0; k < 256; k++) cv = fmaf(dev[k], pW1[(size_t)(256 + k) * 256 + c], cv);
    d_cvec[c] = cv;
}

// ---------------- launch ----------------------------------------------------
extern "C" void kernel_launch(void* const* d_in, const int* in_sizes, int n_in,
                              void* d_out, int out_size) {
    const int*   features = (const int*)  d_in[0];
    const int*   key_ids  = (const int*)  d_in[1];
    const int*   dd_src   = (const int*)  d_in[4];
    const float* emb      = (const float*)d_in[5];
    const float* sage_W   = (const float*)d_in[6];
    const float* sage_b   = (const float*)d_in[7];
    const float* ln_g     = (const float*)d_in[8];
    const float* ln_b     = (const float*)d_in[9];
    const float* dd_W     = (const float*)d_in[10];
    const float* dd_b     = (const float*)d_in[11];
    const float* norm_g   = (const float*)d_in[12];
    const float* norm_b   = (const float*)d_in[13];
    const float* info_W   = (const float*)d_in[14];
    const float* info_b   = (const float*)d_in[15];
    const float* aug      = (const float*)d_in[16];
    const float* pW1      = (const float*)d_in[17];
    const float* pb1      = (const float*)d_in[18];
    const float* pW2      = (const float*)d_in[19];
    const float* pb2      = (const float*)d_in[20];
    float* out = (float*)d_out;

    static bool attr_done = false;
    if (!attr_done) {
        cudaFuncSetAttribute(gemm_fused<2>, cudaFuncAttributeMaxDynamicSharedMemorySize, SMEM_D);
        cudaFuncSetAttribute(gemm_fused<3>, cudaFuncAttributeMaxDynamicSharedMemorySize, SMEM_D);
        cudaFuncSetAttribute(gemm_fused<4>, cudaFuncAttributeMaxDynamicSharedMemorySize, SMEM_D);
        attr_done = true;
    }

    k_init<<<(NMAPC + 255) / 256, 256>>>();
    k_setowner<<<BB / 256, 256>>>(key_ids);
    k_prepW<<<384, 256>>>(sage_W, pW1);
    k_prepEW<<<48, 256>>>(emb, sage_W);
    k_prepEW2<<<6, 256>>>();

    // layer 1: exact fp32 via EW gather (no GEMM)
    k_layer1<<<3 * BB / 8, 256>>>(features, sage_b, ln_g, ln_b);

    gemm_fused<2><<<256, 256, SMEM_D>>>(1, sage_b + 256, ln_g + 256, ln_b + 256,
                                        nullptr, nullptr, nullptr);
    gemm_fused<3><<<128, 256, SMEM_D>>>(2, sage_b + 512, ln_g + 512, ln_b + 512,
                                        nullptr, nullptr, nullptr);

    k_accum<<<64, 256>>>(dd_src);
    k_device<<<1, 256>>>(aug, info_W, info_b, dd_W, dd_b, norm_g, norm_b, pW1, pb1);

    gemm_fused<4><<<128, 256, SMEM_D>>>(3, nullptr, nullptr, nullptr,
                                        pW2, pb2, out);
}

// round 16
// speedup vs baseline: 1.8568x; 1.1835x over previous
#include <cuda_runtime.h>
#include <cuda_fp16.h>

#define BB 8192
#define NMAPC 15625
typedef unsigned int u32;

// ---------------- scratch (static device globals: allocation-free) ----------
__device__ int   d_owner[NMAPC];
__device__ float d_EWp[48 * 256];             // partial emb @ W0 (8 k-chunks)
__device__ float d_EW[6 * 256];               // emb @ sage_W[0]
__device__ float d_h1[(size_t)BB * 3 * 256];
__device__ float d_h2[(size_t)BB * 2 * 256];
__device__ float d_g [(size_t)BB * 256];
__device__ float d_part[64 * 256];
__device__ float d_cvec[256];
// fragment-ordered fp16 weights: [mat][kt(16)][nt(32)][lane(32)][reg(2)] u32
__device__ __align__(16) u32 d_BfragH[4 * 32768];

// ---------------- helpers ---------------------------------------------------
__device__ __forceinline__ float4 f4add(float4 a, float4 b) {
    return make_float4(a.x + b.x, a.y + b.y, a.z + b.z, a.w + b.w);
}
__device__ __forceinline__ u32 pack_hf2(float lo, float hi) {
    __half a = __float2half_rn(lo), b = __float2half_rn(hi);
    return ((u32)__half_as_ushort(b) << 16) | __half_as_ushort(a);
}
__device__ __forceinline__ void mma16816(float* c, const u32* a, const u32* b) {
    asm volatile(
        "mma.sync.aligned.m16n8k16.row.col.f32.f16.f16.f32 "
        "{%0,%1,%2,%3}, {%4,%5,%6,%7}, {%8,%9}, {%0,%1,%2,%3};"
        : "+f"(c[0]), "+f"(c[1]), "+f"(c[2]), "+f"(c[3])
        : "r"(a[0]), "r"(a[1]), "r"(a[2]), "r"(a[3]), "r"(b[0]), "r"(b[1]));
}

// ---------------- small kernels ---------------------------------------------
__global__ void k_init() {
    int i = blockIdx.x * 256 + threadIdx.x;
    if (i < NMAPC) d_owner[i] = -1;
}
__global__ void k_setowner(const int* __restrict__ key_ids) {
    int b = blockIdx.x * 256 + threadIdx.x;
    if (b < BB) {
        const int* kd = key_ids + b * 6;
        int idx = kd[0]*3125 + kd[1]*625 + kd[2]*125 + kd[3]*25 + kd[4]*5 + kd[5];
        d_owner[idx] = b;
    }
}
// EW partials: block = (e * 8 + chunk), k-range [chunk*32, chunk*32+32)
__global__ void k_prepEW(const float* __restrict__ emb, const float* __restrict__ W0) {
    __shared__ float er[32];
    int e = blockIdx.x >> 3, ch = blockIdx.x & 7, c = threadIdx.x;
    int k0 = ch * 32;
    if (c < 32) er[c] = emb[e * 256 + k0 + c];
    __syncthreads();
    float acc = 0.f;
#pragma unroll
    for (int k = 0; k < 32; k++) acc = fmaf(er[k], W0[(size_t)(k0 + k) * 256 + c], acc);
    d_EWp[blockIdx.x * 256 + c] = acc;
}
__global__ void k_prepEW2(void) {
    int e = blockIdx.x, c = threadIdx.x;
    float s = 0.f;
#pragma unroll
    for (int ch = 0; ch < 8; ch++) s += d_EWp[(e * 8 + ch) * 256 + c];
    d_EW[e * 256 + c] = s;
}
// layer 1 = gather-add of EW rows + bias -> LN -> ReLU   (warp per row)
__global__ void k_layer1(const int* __restrict__ features,
                         const float* __restrict__ bias,
                         const float* __restrict__ gamma,
                         const float* __restrict__ beta) {
    int warp = threadIdx.x >> 5, lane = threadIdx.x & 31;
    int m = blockIdx.x * 8 + warp;          // < 24576
    int b = m / 3, j = m - 3 * b;
    const int* f = features + b * 9;
    int lo = (j == 0) ? 0 : (j - 1);
    bool three = (j != 0);
    float scl = three ? (1.f / 3.f) : 0.5f;
    const float* e0 = d_EW + f[lo] * 256;
    const float* e1 = d_EW + f[lo + 1] * 256;
    const float* e2 = three ? (d_EW + f[lo + 2] * 256) : e1;
    float v[8], s = 0.f, q = 0.f;
#pragma unroll
    for (int i = 0; i < 8; i++) {
        int c = lane + 32 * i;
        float x = e0[c] + e1[c];
        if (three) x += e2[c];
        x = x * scl + bias[c];
        v[i] = x; s += x; q += x * x;
    }
#pragma unroll
    for (int o = 16; o > 0; o >>= 1) {
        s += __shfl_xor_sync(0xffffffffu, s, o);
        q += __shfl_xor_sync(0xffffffffu, q, o);
    }
    float mean = s * (1.f / 256.f);
    float var  = q * (1.f / 256.f) - mean * mean;
    float rsd  = rsqrtf(var + 1e-5f);
#pragma unroll
    for (int i = 0; i < 8; i++) {
        int c = lane + 32 * i;
        d_h1[(size_t)m * 256 + c] = fmaxf((v[i] - mean) * rsd * gamma[c] + beta[c], 0.f);
    }
}
// W -> fp16 fragment images (mma m16n8k16 B-layout, per-lane order)
__global__ void k_prepW(const float* __restrict__ sage_W, const float* __restrict__ pW1) {
    int t = blockIdx.x * 256 + threadIdx.x;   // 98304 threads: mats 1..3
    int rg  = t & 1;
    int l   = (t >> 1) & 31;
    int nt  = (t >> 6) & 31;
    int kt  = (t >> 11) & 15;
    int mat = (t >> 15) + 1;                  // 1..3
    const float* src = (mat < 3) ? (sage_W + (size_t)mat * 65536) : pW1;
    int n  = nt * 8 + (l >> 2);
    int k0 = kt * 16 + (l & 3) * 2 + rg * 8;
    float x0 = src[(size_t)k0 * 256 + n];
    float x1 = src[(size_t)(k0 + 1) * 256 + n];
    int di = mat * 32768 + ((kt * 32 + nt) * 32 + l) * 2 + rg;
    d_BfragH[di] = pack_hf2(x0, x1);
}

// ---------------- fused HMMA GEMM (fp16 single-pass) ------------------------
// CTA: 64 rows x 256 cols. 8 warps = 2(M) x 4(N), warp tile 32x64.
#define AH_OFF 0
#define SS_OFF 33792
#define SMEM_D (33792 + 2048 + 512)

template<int MODE>
__global__ __launch_bounds__(256, 2) void gemm_fused(
    int mat,
    const float* __restrict__ bias, const float* __restrict__ gamma, const float* __restrict__ beta,
    const float* __restrict__ w2, const float* __restrict__ w2b,
    float* __restrict__ outp)
{
    extern __shared__ __align__(16) char smem[];
    u32* ah32 = (u32*)(smem + AH_OFF);          // [64][264] fp16 viewed as u32 pairs
    float* ssum  = (float*)(smem + SS_OFF);     // [4][64]
    float* ssq   = ssum + 256;                  // [4][64]
    float* meanv = ssq + 256;                   // [64]
    float* rsdv  = meanv + 64;                  // [64]

    const int tid = threadIdx.x, lane = tid & 31, warp = tid >> 5;
    const int wm = warp >> 2, wn = warp & 3;
    const int m0 = blockIdx.x * 64;

    // ---- A prologue: aggregate fp32, convert fp16, stage in smem
    {
        int row = tid >> 2, cb = (tid & 3) * 64;
        int m = m0 + row;
        const float* s0; const float* s1 = nullptr; const float* s2 = nullptr;
        float scl = 1.f;
        if (MODE == 2) {
            const float* base = d_h1 + (size_t)(m >> 1) * 768;
            s0 = base; s1 = base + 256;
            if (m & 1) s2 = base + 512;
            scl = (m & 1) ? (1.f / 3.f) : 0.5f;
        } else if (MODE == 3) {
            const float* base = d_h2 + (size_t)m * 512;
            s0 = base; s1 = base + 256; scl = 0.5f;
        } else {
            s0 = d_g + (size_t)m * 256;
        }
#pragma unroll
        for (int i = 0; i < 16; i++) {
            float4 a = *(const float4*)&s0[cb + 4 * i];
            if (MODE != 4) {
                a = f4add(a, *(const float4*)&s1[cb + 4 * i]);
                if (s2) a = f4add(a, *(const float4*)&s2[cb + 4 * i]);
                a.x *= scl; a.y *= scl; a.z *= scl; a.w *= scl;
            }
            int off = row * 264 + cb + 4 * i;      // fp16 offset, even
            ah32[(off >> 1)]     = pack_hf2(a.x, a.y);
            ah32[(off >> 1) + 1] = pack_hf2(a.z, a.w);
        }
    }
    __syncthreads();

    // ---- main loop with 1-deep register prefetch of B fragments
    float acc[2][8][4];
#pragma unroll
    for (int mt = 0; mt < 2; mt++)
#pragma unroll
        for (int nt = 0; nt < 8; nt++)
#pragma unroll
            for (int q = 0; q < 4; q++) acc[mt][nt][q] = 0.f;

    const int bbase = mat * 32768 + ((wn * 8) * 32 + lane) * 2;   // + kt*2048 + nt*64
    const u32* BH = d_BfragH + bbase;
    const int arow = wm * 32 + (lane >> 2);

    u32 bh[2][8][2];
#pragma unroll
    for (int nt = 0; nt < 8; nt++) {
        uint2 vh = *(const uint2*)&BH[nt * 64];
        bh[0][nt][0] = vh.x; bh[0][nt][1] = vh.y;
    }

#pragma unroll
    for (int kt = 0; kt < 16; kt++) {
        const int cur = kt & 1, nxt = cur ^ 1;
        if (kt < 15) {
            int o = (kt + 1) * 2048;
#pragma unroll
            for (int nt = 0; nt < 8; nt++) {
                uint2 vh = *(const uint2*)&BH[o + nt * 64];
                bh[nxt][nt][0] = vh.x; bh[nxt][nt][1] = vh.y;
            }
        }
        u32 ah[2][4];
        int acol = kt * 16 + (lane & 3) * 2;
#pragma unroll
        for (int mt = 0; mt < 2; mt++) {
            int base = (arow + mt * 16) * 264 + acol;   // fp16 offset (even)
            ah[mt][0] = ah32[(base) >> 1];
            ah[mt][1] = ah32[(base + 8 * 264) >> 1];
            ah[mt][2] = ah32[(base + 8) >> 1];
            ah[mt][3] = ah32[(base + 8 * 264 + 8) >> 1];
        }
#pragma unroll
        for (int mt = 0; mt < 2; mt++)
#pragma unroll
            for (int nt = 0; nt < 8; nt++)
                mma16816(acc[mt][nt], ah[mt], bh[cur][nt]);
    }

    // ---- epilogue
    if (MODE <= 3) {
        float bv[8][2];
#pragma unroll
        for (int nt = 0; nt < 8; nt++) {
            int c = wn * 64 + nt * 8 + (lane & 3) * 2;
            bv[nt][0] = bias[c]; bv[nt][1] = bias[c + 1];
        }
#pragma unroll
        for (int mt = 0; mt < 2; mt++) {
            float sL = 0.f, qL = 0.f, sH = 0.f, qH = 0.f;
#pragma unroll
            for (int nt = 0; nt < 8; nt++) {
                float v0 = acc[mt][nt][0] + bv[nt][0], v1 = acc[mt][nt][1] + bv[nt][1];
                float v2 = acc[mt][nt][2] + bv[nt][0], v3 = acc[mt][nt][3] + bv[nt][1];
                sL += v0 + v1; qL += v0 * v0 + v1 * v1;
                sH += v2 + v3; qH += v2 * v2 + v3 * v3;
            }
#pragma unroll
            for (int o = 1; o <= 2; o <<= 1) {
                sL += __shfl_xor_sync(0xffffffffu, sL, o);
                qL += __shfl_xor_sync(0xffffffffu, qL, o);
                sH += __shfl_xor_sync(0xffffffffu, sH, o);
                qH += __shfl_xor_sync(0xffffffffu, qH, o);
            }
            if ((lane & 3) == 0) {
                int r = wm * 32 + mt * 16 + (lane >> 2);
                ssum[wn * 64 + r] = sL;     ssq[wn * 64 + r] = qL;
                ssum[wn * 64 + r + 8] = sH; ssq[wn * 64 + r + 8] = qH;
            }
        }
        __syncthreads();
        if (tid < 64) {
            float s  = ssum[tid] + ssum[64 + tid] + ssum[128 + tid] + ssum[192 + tid];
            float q  = ssq[tid]  + ssq[64 + tid]  + ssq[128 + tid]  + ssq[192 + tid];
            float mean = s * (1.f / 256.f);
            float var  = q * (1.f / 256.f) - mean * mean;
            meanv[tid] = mean;
            rsdv[tid]  = rsqrtf(var + 1e-5f);
        }
        __syncthreads();
        float* O = (MODE == 2) ? d_h2 : d_g;
#pragma unroll
        for (int mt = 0; mt < 2; mt++) {
            int r = wm * 32 + mt * 16 + (lane >> 2);
            float mn0 = meanv[r], rs0 = rsdv[r];
            float mn1 = meanv[r + 8], rs1 = rsdv[r + 8];
#pragma unroll
            for (int nt = 0; nt < 8; nt++) {
                int c = wn * 64 + nt * 8 + (lane & 3) * 2;
                float g0 = gamma[c], g1 = gamma[c + 1];
                float b0 = beta[c],  b1 = beta[c + 1];
                float v0 = acc[mt][nt][0] + bv[nt][0], v1 = acc[mt][nt][1] + bv[nt][1];
                float v2 = acc[mt][nt][2] + bv[nt][0], v3 = acc[mt][nt][3] + bv[nt][1];
                float2 oL = make_float2(fmaxf((v0 - mn0) * rs0 * g0 + b0, 0.f),
                                        fmaxf((v1 - mn0) * rs0 * g1 + b1, 0.f));
                float2 oH = make_float2(fmaxf((v2 - mn1) * rs1 * g0 + b0, 0.f),
                                        fmaxf((v3 - mn1) * rs1 * g1 + b1, 0.f));
                *(float2*)&O[(size_t)(m0 + r) * 256 + c]     = oL;
                *(float2*)&O[(size_t)(m0 + r + 8) * 256 + c] = oH;
            }
        }
    } else {
        float cv[8][2], wv[8][2];
#pragma unroll
        for (int nt = 0; nt < 8; nt++) {
            int c = wn * 64 + nt * 8 + (lane & 3) * 2;
            cv[nt][0] = d_cvec[c]; cv[nt][1] = d_cvec[c + 1];
            wv[nt][0] = w2[c];     wv[nt][1] = w2[c + 1];
        }
#pragma unroll
        for (int mt = 0; mt < 2; mt++) {
            float pL = 0.f, pH = 0.f;
#pragma unroll
            for (int nt = 0; nt < 8; nt++) {
                pL = fmaf(fmaxf(acc[mt][nt][0] + cv[nt][0], 0.f), wv[nt][0], pL);
                pL = fmaf(fmaxf(acc[mt][nt][1] + cv[nt][1], 0.f), wv[nt][1], pL);
                pH = fmaf(fmaxf(acc[mt][nt][2] + cv[nt][0], 0.f), wv[nt][0], pH);
                pH = fmaf(fmaxf(acc[mt][nt][3] + cv[nt][1], 0.f), wv[nt][1], pH);
            }
#pragma unroll
            for (int o = 1; o <= 2; o <<= 1) {
                pL += __shfl_xor_sync(0xffffffffu, pL, o);
                pH += __shfl_xor_sync(0xffffffffu, pH, o);
            }
            if ((lane & 3) == 0) {
                int r = wm * 32 + mt * 16 + (lane >> 2);
                ssum[wn * 64 + r] = pL;
                ssum[wn * 64 + r + 8] = pH;
            }
        }
        __syncthreads();
        if (tid < 64)
            outp[m0 + tid] = ssum[tid] + ssum[64 + tid] + ssum[128 + tid] + ssum[192 + tid]
                           + w2b[0];
    }
}

// ---------------- dnn-device graph ------------------------------------------
__global__ void k_accum(const int* __restrict__ dd_src) {
    int c = threadIdx.x;
    int e0 = blockIdx.x * 32;
    float loc = 0.f;
    for (int i = 0; i < 32; i++) {
        int o = d_owner[dd_src[e0 + i]];
        if (o >= 0) loc += d_g[(size_t)o * 256 + c];
    }
    d_part[blockIdx.x * 256 + c] = loc;
}

// 1024 threads: c = tid&255, ch = tid>>8 (4 k-chunks of 64)
__global__ __launch_bounds__(1024) void k_device(
        const float* __restrict__ aug,  const float* __restrict__ infoW,
        const float* __restrict__ infob,
        const float* __restrict__ ddW,  const float* __restrict__ ddb,
        const float* __restrict__ ng,   const float* __restrict__ nb,
        const float* __restrict__ pW1,  const float* __restrict__ pb1) {
    __shared__ float t[256], row[256], dev[256], red[1024], rsum[8], rssq[8], stats[2];
    int tid = threadIdx.x, c = tid & 255, ch = tid >> 8;
    int lane = tid & 31, warp = tid >> 5;

    // Phase A: t[c] = (agg + info)/2049; agg split over 4x16 partials
    float a = 0.f;
#pragma unroll
    for (int i = 0; i < 16; i++) a += d_part[(ch * 16 + i) * 256 + c];
    red[tid] = a;
    __syncthreads();
    if (ch == 0) {
        float agg = red[c] + red[c + 256] + red[c + 512] + red[c + 768];
        float info = infob[c];
#pragma unroll
        for (int j = 0; j < 5; j++) info = fmaf(aug[j], infoW[j * 256 + c], info);
        t[c] = (agg + info) * (1.f / 2049.f);
    }
    __syncthreads();

    // Phase B: row = t @ ddW + ddb (split-k x4)
    {
        float acc = 0.f;
        const float* Wp = ddW + (size_t)(ch * 64) * 256 + c;
#pragma unroll 8
        for (int k = 0; k < 64; k++) acc = fmaf(t[ch * 64 + k], Wp[(size_t)k * 256], acc);
        red[tid] = acc;
    }
    __syncthreads();
    if (ch == 0) row[c] = red[c] + red[c + 256] + red[c + 512] + red[c + 768] + ddb[c];
    __syncthreads();

    // Phase C: LN stats over row[0..255] (first 256 threads, 8 warps)
    if (tid < 256) {
        float v = row[tid], s = v, q = v * v;
#pragma unroll
        for (int o = 16; o > 0; o >>= 1) {
            s += __shfl_xor_sync(0xffffffffu, s, o);
            q += __shfl_xor_sync(0xffffffffu, q, o);
        }
        if (lane == 0) { rsum[warp] = s; rssq[warp] = q; }
    }
    __syncthreads();
    if (tid == 0) {
        float S = 0.f, Q = 0.f;
#pragma unroll
        for (int i = 0; i < 8; i++) { S += rsum[i]; Q += rssq[i]; }
        float mean = S * (1.f / 256.f);
        float var  = Q * (1.f / 256.f) - mean * mean;
        stats[0] = mean; stats[1] = rsqrtf(var + 1e-5f);
    }
    __syncthreads();
    if (ch == 0)
        dev[c] = fmaxf((row[c] - stats[0]) * stats[1] * ng[c] + nb[c], 0.f);
    __syncthreads();

    // Phase D: cvec = dev @ pW1[256:512] + pb1 (split-k x4)
    {
        float cv = 0.f;
        const float* Wp = pW1 + (size_t)(256 + ch * 64) * 256 + c;
#pragma unroll 8
        for (int k = 0; k < 64; k++) cv = fmaf(dev[ch * 64 + k], Wp[(size_t)k * 256], cv);
        red[tid] = cv;
    }
    __syncthreads();
    if (ch == 0) d_cvec[c] = red[c] + red[c + 256] + red[c + 512] + red[c + 768] + pb1[c];
}

// ---------------- launch ----------------------------------------------------
extern "C" void kernel_launch(void* const* d_in, const int* in_sizes, int n_in,
                              void* d_out, int out_size) {
    const int*   features = (const int*)  d_in[0];
    const int*   key_ids  = (const int*)  d_in[1];
    const int*   dd_src   = (const int*)  d_in[4];
    const float* emb      = (const float*)d_in[5];
    const float* sage_W   = (const float*)d_in[6];
    const float* sage_b   = (const float*)d_in[7];
    const float* ln_g     = (const float*)d_in[8];
    const float* ln_b     = (const float*)d_in[9];
    const float* dd_W     = (const float*)d_in[10];
    const float* dd_b     = (const float*)d_in[11];
    const float* norm_g   = (const float*)d_in[12];
    const float* norm_b   = (const float*)d_in[13];
    const float* info_W   = (const float*)d_in[14];
    const float* info_b   = (const float*)d_in[15];
    const float* aug      = (const float*)d_in[16];
    const float* pW1      = (const float*)d_in[17];
    const float* pb1      = (const float*)d_in[18];
    const float* pW2      = (const float*)d_in[19];
    const float* pb2      = (const float*)d_in[20];
    float* out = (float*)d_out;

    static bool attr_done = false;
    if (!attr_done) {
        cudaFuncSetAttribute(gemm_fused<2>, cudaFuncAttributeMaxDynamicSharedMemorySize, SMEM_D);
        cudaFuncSetAttribute(gemm_fused<3>, cudaFuncAttributeMaxDynamicSharedMemorySize, SMEM_D);
        cudaFuncSetAttribute(gemm_fused<4>, cudaFuncAttributeMaxDynamicSharedMemorySize, SMEM_D);
        attr_done = true;
    }

    k_init<<<(NMAPC + 255) / 256, 256>>>();
    k_setowner<<<BB / 256, 256>>>(key_ids);
    k_prepW<<<384, 256>>>(sage_W, pW1);
    k_prepEW<<<48, 256>>>(emb, sage_W);
    k_prepEW2<<<6, 256>>>();

    // layer 1: exact fp32 via EW gather (no GEMM)
    k_layer1<<<3 * BB / 8, 256>>>(features, sage_b, ln_g, ln_b);

    gemm_fused<2><<<256, 256, SMEM_D>>>(1, sage_b + 256, ln_g + 256, ln_b + 256,
                                        nullptr, nullptr, nullptr);
    gemm_fused<3><<<128, 256, SMEM_D>>>(2, sage_b + 512, ln_g + 512, ln_b + 512,
                                        nullptr, nullptr, nullptr);

    k_accum<<<64, 256>>>(dd_src);
    k_device<<<1, 1024>>>(aug, info_W, info_b, dd_W, dd_b, norm_g, norm_b, pW1, pb1);

    gemm_fused<4><<<128, 256, SMEM_D>>>(3, nullptr, nullptr, nullptr,
                                        pW2, pb2, out);
}